// round 5
// baseline (speedup 1.0000x reference)
#include <cuda_runtime.h>
#include <cuda_bf16.h>
#include <cstdint>
#include <cstddef>

#define TT 1024
#define BB 8
#define DD 1024
#define HH 16
#define DHD 64
#define FFD 4096
#define TB (TT*BB)          // 8192
#define BH (BB*HH)          // 128

// ---------------------------------------------------------------------------
// Scratch
// ---------------------------------------------------------------------------
__device__ float g_ln  [(size_t)TB * DD];
__device__ float g_qkv [(size_t)TB * 3 * DD];
__device__ float g_rk  [(size_t)TT * DD];
__device__ float g_bd  [(size_t)BH * TT * TT];
__device__ float g_attn[(size_t)TB * DD];
__device__ float g_h1  [(size_t)TB * FFD];
__device__ float g_qw  [(size_t)BH * TT * DHD];
__device__ float g_qr  [(size_t)BH * TT * DHD];
__device__ float g_vt  [(size_t)BH * DHD * TT];
__device__ float g_posr[(size_t)TT * DD];
__device__ float g_wqkv[(size_t)3 * DD * DD];
__device__ float g_wr  [(size_t)DD * DD];
__device__ float g_wo  [(size_t)DD * DD];
__device__ float g_wf1 [(size_t)FFD * DD];
__device__ float g_wf2 [(size_t)DD * FFD];

// ---------------------------------------------------------------------------
// Helpers
// ---------------------------------------------------------------------------
__device__ __forceinline__ uint32_t f2tf(float x){
    uint32_t u; asm("cvt.rna.tf32.f32 %0, %1;" : "=r"(u) : "f"(x)); return u;
}
__device__ __forceinline__ float roundtf(float x){ return __uint_as_float(f2tf(x)); }
__device__ __forceinline__ void mma8(float* d, const uint32_t* a, const uint32_t* b){
    asm volatile("mma.sync.aligned.m16n8k8.row.col.f32.tf32.tf32.f32 "
        "{%0,%1,%2,%3}, {%4,%5,%6,%7}, {%8,%9}, {%0,%1,%2,%3};\n"
        : "+f"(d[0]),"+f"(d[1]),"+f"(d[2]),"+f"(d[3])
        : "r"(a[0]),"r"(a[1]),"r"(a[2]),"r"(a[3]),"r"(b[0]),"r"(b[1]));
}
// ldmatrix x4 on tf32 data aliased as b16: gives 4 8x4-tf32 tiles in mma frag layout
__device__ __forceinline__ void ldm4(uint32_t* r, uint32_t addr){
    asm volatile("ldmatrix.sync.aligned.m8n8.x4.shared.b16 {%0,%1,%2,%3}, [%4];"
        : "=r"(r[0]),"=r"(r[1]),"=r"(r[2]),"=r"(r[3]) : "r"(addr));
}
__device__ __forceinline__ void cp16(uint32_t dst, const float* src){
    asm volatile("cp.async.cg.shared.global [%0], [%1], 16;\n" :: "r"(dst), "l"(src));
}
#define CP_COMMIT() asm volatile("cp.async.commit_group;\n")
#define CP_WAIT(n)  asm volatile("cp.async.wait_group %0;\n" :: "n"(n))
__device__ __forceinline__ uint32_t s2u(const void* p){
    return (uint32_t)__cvta_generic_to_shared(p);
}

// ---------------------------------------------------------------------------
// Fused tf32-round convert for all weights + pos (one launch)
// ---------------------------------------------------------------------------
struct CvtArgs { const float* src[6]; float* dst[6]; };
__global__ __launch_bounds__(256) void cvt_multi(CvtArgs a)
{
    // float4 counts: qkv_w 786432 | r_w 262144 | o_w 262144 | f1 1048576 | f2 1048576 | pos 262144
    const int g = blockIdx.x * 256 + threadIdx.x;
    int idx = g, r = 0;
    if      (idx < 786432)  { r = 0; }
    else if (idx < 1048576) { r = 1; idx -= 786432; }
    else if (idx < 1310720) { r = 2; idx -= 1048576; }
    else if (idx < 2359296) { r = 3; idx -= 1310720; }
    else if (idx < 3407872) { r = 4; idx -= 2359296; }
    else                    { r = 5; idx -= 3407872; }
    float4 v = reinterpret_cast<const float4*>(a.src[r])[idx];
    v.x = roundtf(v.x); v.y = roundtf(v.y); v.z = roundtf(v.z); v.w = roundtf(v.w);
    reinterpret_cast<float4*>(a.dst[r])[idx] = v;
}

// ---------------------------------------------------------------------------
// Q prep: Qw = round(q + rwb), Qr = round(q + rrb), packed [bh][i][64]
// ---------------------------------------------------------------------------
__global__ __launch_bounds__(256) void qprep_kernel(
    const float* __restrict__ qkv, const float* __restrict__ rwb,
    const float* __restrict__ rrb, float* __restrict__ Qw, float* __restrict__ Qr)
{
    const int g = blockIdx.x * 256 + threadIdx.x;
    const int bh = g >> 14;
    const int rem = g & 16383;
    const int i = rem >> 4, d4 = rem & 15;
    const int b = bh >> 4, h = bh & 15;
    float4 v = *reinterpret_cast<const float4*>(qkv + ((size_t)i*BB + b)*(3*DD) + h*DHD + d4*4);
    float4 w = reinterpret_cast<const float4*>(rwb)[h*16 + d4];
    float4 r = reinterpret_cast<const float4*>(rrb)[h*16 + d4];
    float4 ow, orr;
    ow.x = roundtf(v.x + w.x); ow.y = roundtf(v.y + w.y);
    ow.z = roundtf(v.z + w.z); ow.w = roundtf(v.w + w.w);
    orr.x = roundtf(v.x + r.x); orr.y = roundtf(v.y + r.y);
    orr.z = roundtf(v.z + r.z); orr.w = roundtf(v.w + r.w);
    reinterpret_cast<float4*>(Qw)[g] = ow;
    reinterpret_cast<float4*>(Qr)[g] = orr;
}

// ---------------------------------------------------------------------------
// V transpose: vT[bh][d][t]
// ---------------------------------------------------------------------------
__global__ __launch_bounds__(256) void vtrans(
    const float* __restrict__ qkv, float* __restrict__ vT)
{
    const int bh = blockIdx.y, b = bh >> 4, h = bh & 15;
    const int k0 = blockIdx.x * 64;
    __shared__ float t[64][65];
    const int tid = threadIdx.x;
    const int kr = tid >> 4;
    const int c4 = (tid & 15) * 4;
    #pragma unroll
    for (int u = 0; u < 4; u++){
        const int k = kr + u*16;
        float4 v = *(const float4*)(qkv + ((size_t)(k0 + k)*BB + b)*(3*DD) + 2*DD + h*DHD + c4);
        t[k][c4+0] = v.x; t[k][c4+1] = v.y; t[k][c4+2] = v.z; t[k][c4+3] = v.w;
    }
    __syncthreads();
    #pragma unroll
    for (int u = 0; u < 4; u++){
        const int j = kr + u*16;
        float4 o;
        o.x = t[c4+0][j]; o.y = t[c4+1][j]; o.z = t[c4+2][j]; o.w = t[c4+3][j];
        *(float4*)(vT + ((size_t)bh*DHD + j)*TT + k0 + c4) = o;
    }
}

// ---------------------------------------------------------------------------
// 4-stage cp.async GEMM mainloop with ldmatrix fragments.
// acc[64] += A[128xK] @ B[128xK]^T. smem: As[4][128][20] | Bs[4][128][20]
// = 20480 floats = 81920 B
// ---------------------------------------------------------------------------
__device__ __forceinline__ void gemm_mainloop(
    const float* __restrict__ Ab, int lda,
    const float* __restrict__ Bb, int ldb,
    int K, float* acc, float* sm)
{
    const int tid = threadIdx.x;
    const int lr = tid >> 1, cs = (tid & 1) * 8;
    float* As = sm;
    float* Bs = sm + 4 * 2560;
    const uint32_t aBase = s2u(As), bBase = s2u(Bs);
    const float* apn = Ab + (size_t)lr * lda + cs;
    const float* bpn = Bb + (size_t)lr * ldb + cs;

    auto issue = [&](int s, int k0){
        uint32_t da = aBase + (uint32_t)(s*2560 + lr*20 + cs)*4;
        cp16(da, apn + k0); cp16(da + 16, apn + k0 + 4);
        uint32_t db = bBase + (uint32_t)(s*2560 + lr*20 + cs)*4;
        cp16(db, bpn + k0); cp16(db + 16, bpn + k0 + 4);
    };
    #pragma unroll
    for (int s = 0; s < 3; s++){
        if (s*16 < K) issue(s, s*16);
        CP_COMMIT();
    }

    const int lane = tid & 31, w = tid >> 5;
    const int wm = (w >> 2) * 64, wn = (w & 3) * 32;
    // ldmatrix lane address components
    const int arow = (lane & 7) + ((lane >> 3) & 1)*8;
    const int acol = (lane >> 4) * 4;
    const int brow = (lane & 7) + ((lane >> 4) & 1)*8;
    const int bcol = ((lane >> 3) & 1) * 4;
    const uint32_t aFrag = aBase + (uint32_t)((wm + arow)*20 + acol)*4;
    const uint32_t bFrag = bBase + (uint32_t)((wn + brow)*20 + bcol)*4;

    for (int k0 = 0, t = 0; k0 < K; k0 += 16, t++){
        CP_WAIT(2);
        __syncthreads();
        const int kn = k0 + 48;
        if (kn < K) issue((t + 3) & 3, kn);
        CP_COMMIT();
        const uint32_t aB = aFrag + (t & 3)*10240;
        const uint32_t bB = bFrag + (t & 3)*10240;
        #pragma unroll
        for (int kk = 0; kk < 16; kk += 8){
            uint32_t af[4][4], bf[4][2];
            #pragma unroll
            for (int mi = 0; mi < 4; mi++)
                ldm4(af[mi], aB + (uint32_t)(mi*16*20 + kk)*4);
            #pragma unroll
            for (int p = 0; p < 2; p++){
                uint32_t q[4];
                ldm4(q, bB + (uint32_t)(p*16*20 + kk)*4);
                bf[2*p][0] = q[0]; bf[2*p][1] = q[1];
                bf[2*p+1][0] = q[2]; bf[2*p+1][1] = q[3];
            }
            #pragma unroll
            for (int mi = 0; mi < 4; mi++)
                #pragma unroll
                for (int ni = 0; ni < 4; ni++)
                    mma8(acc + (mi*4 + ni)*4, af[mi], bf[ni]);
        }
    }
}

// ---------------------------------------------------------------------------
// Dense GEMM. EPI: 0 store, 1 +bias relu, 2 +bias +res, 3 +res. ROUND: tf32 out
// ---------------------------------------------------------------------------
template<int EPI, int ROUND>
__global__ __launch_bounds__(256, 1) void gemm_async(
    const float* __restrict__ A, const float* __restrict__ B, float* __restrict__ C,
    int N, int K, const float* __restrict__ biasN, const float* __restrict__ res)
{
    extern __shared__ float sm[];
    float acc[64];
    #pragma unroll
    for (int i = 0; i < 64; i++) acc[i] = 0.f;
    gemm_mainloop(A + (size_t)blockIdx.y*128*K, K,
                  B + (size_t)blockIdx.x*128*K, K, K, acc, sm);

    const int lane = threadIdx.x & 31, w = threadIdx.x >> 5;
    const int wm = (w >> 2) * 64, wn = (w & 3) * 32;
    float* Cb = C + (size_t)blockIdx.y*128*N + blockIdx.x*128;
    const float* rb = res ? res + (size_t)blockIdx.y*128*N + blockIdx.x*128 : nullptr;
    #pragma unroll
    for (int mi = 0; mi < 4; mi++)
        #pragma unroll
        for (int ni = 0; ni < 4; ni++){
            const float* a = acc + (mi*4 + ni)*4;
            const int r0 = wm + mi*16 + (lane >> 2);
            const int c0 = wn + ni*8 + 2*(lane & 3);
            #pragma unroll
            for (int half = 0; half < 2; half++){
                const int r = r0 + 8*half;
                float v0 = a[half*2 + 0], v1 = a[half*2 + 1];
                if (EPI == 1){
                    v0 += biasN[blockIdx.x*128 + c0];     v0 = fmaxf(v0, 0.f);
                    v1 += biasN[blockIdx.x*128 + c0 + 1]; v1 = fmaxf(v1, 0.f);
                }
                if (EPI == 2){
                    v0 += biasN[blockIdx.x*128 + c0]     + rb[(size_t)r*N + c0];
                    v1 += biasN[blockIdx.x*128 + c0 + 1] + rb[(size_t)r*N + c0 + 1];
                }
                if (EPI == 3){
                    v0 += rb[(size_t)r*N + c0];
                    v1 += rb[(size_t)r*N + c0 + 1];
                }
                if (ROUND){ v0 = roundtf(v0); v1 = roundtf(v1); }
                float2 o = {v0, v1};
                *(float2*)(Cb + (size_t)r*N + c0) = o;
            }
        }
}

// ---------------------------------------------------------------------------
// BD_pre: BD[bh][i][m] = Qr[bh][i] . rk[m][h*64..]
// ---------------------------------------------------------------------------
__global__ __launch_bounds__(256, 1) void bd_async(
    const float* __restrict__ Qr, const float* __restrict__ rk, float* __restrict__ BD)
{
    extern __shared__ float sm[];
    const int bh = blockIdx.z, h = bh & 15;
    float acc[64];
    #pragma unroll
    for (int i = 0; i < 64; i++) acc[i] = 0.f;
    gemm_mainloop(Qr + ((size_t)bh*TT + blockIdx.y*128)*DHD, DHD,
                  rk + (size_t)blockIdx.x*128*DD + h*DHD, DD, DHD, acc, sm);

    const int lane = threadIdx.x & 31, w = threadIdx.x >> 5;
    const int wm = (w >> 2) * 64, wn = (w & 3) * 32;
    float* Cb = BD + ((size_t)bh*TT + blockIdx.y*128)*TT + blockIdx.x*128;
    #pragma unroll
    for (int mi = 0; mi < 4; mi++)
        #pragma unroll
        for (int ni = 0; ni < 4; ni++){
            const float* a = acc + (mi*4 + ni)*4;
            const int r0 = wm + mi*16 + (lane >> 2);
            const int c0 = wn + ni*8 + 2*(lane & 3);
            #pragma unroll
            for (int half = 0; half < 2; half++){
                float2 o = {a[half*2], a[half*2 + 1]};
                *(float2*)(Cb + (size_t)(r0 + 8*half)*TT + c0) = o;
            }
        }
}

// ---------------------------------------------------------------------------
// Fused flash attention with rel-shift (ldmatrix fragments, Q in registers).
// grid (8 i-tiles, 128 bh), 256 threads.
// smem floats: Qs[128*68]=8704 | Ks[2][128*68]=17408 | Vs[64*132]=8448 | Ps[128*132]=16896
// ---------------------------------------------------------------------------
__global__ __launch_bounds__(256, 1) void flash_attn(
    const float* __restrict__ Qw, const float* __restrict__ qkv,
    const float* __restrict__ vT, const float* __restrict__ BD,
    float* __restrict__ attn)
{
    extern __shared__ float sm[];
    float* Qs = sm;                 // [128][68]
    float* Ks = sm + 8704;          // [2][128][68]
    float* Vs = sm + 26112;         // [64][132]
    float* Ps = sm + 34560;         // [128][132]
    const uint32_t qB = s2u(Qs), kB = s2u(Ks), vB = s2u(Vs), pB = s2u(Ps);

    const int bh = blockIdx.y, b = bh >> 4, h = bh & 15;
    const int i0 = blockIdx.x * 128;
    const int tid = threadIdx.x, lane = tid & 31, w = tid >> 5;
    const int gr = lane >> 2, tg = lane & 3;
    const int wm = w * 16;

    // ldmatrix lane address components
    const int arow = (lane & 7) + ((lane >> 3) & 1)*8;
    const int acol = (lane >> 4) * 4;
    const int brow = (lane & 7) + ((lane >> 4) & 1)*8;
    const int bcol = ((lane >> 3) & 1) * 4;

    const int klr = tid >> 1, kc0 = (tid & 1) * 32;
    const int vr  = tid >> 2, vc0 = (tid & 3) * 32;

    const float* Qsrc = Qw + ((size_t)bh*TT + i0 + klr)*DHD + kc0;
    const float* Ksrc = qkv + ((size_t)klr*BB + b)*(3*DD) + DD + h*DHD + kc0;
    const size_t kRowStride = (size_t)BB*3*DD;
    const float* Vsrc = vT + ((size_t)bh*DHD + vr)*TT + vc0;

    auto issueQ = [&](){
        uint32_t d = qB + (uint32_t)(klr*68 + kc0)*4;
        #pragma unroll
        for (int u = 0; u < 8; u++) cp16(d + u*16, Qsrc + u*4);
    };
    auto issueK = [&](int slot, int jt){
        if (jt < 8){
            const float* src = Ksrc + (size_t)jt*128*kRowStride;
            uint32_t d = kB + (uint32_t)(slot*8704 + klr*68 + kc0)*4;
            #pragma unroll
            for (int u = 0; u < 8; u++) cp16(d + u*16, src + u*4);
        }
    };
    auto issueV = [&](int jt){
        if (jt < 8){
            const float* src = Vsrc + jt*128;
            uint32_t d = vB + (uint32_t)(vr*132 + vc0)*4;
            #pragma unroll
            for (int u = 0; u < 8; u++) cp16(d + u*16, src + u*4);
        }
    };

    issueQ(); issueK(0, 0); CP_COMMIT();
    issueV(0);              CP_COMMIT();
    issueK(1, 1);           CP_COMMIT();

    float m_lo = -1e30f, m_hi = -1e30f, l_lo = 0.f, l_hi = 0.f;
    float acc_o[8][4];
    #pragma unroll
    for (int i = 0; i < 8; i++)
        #pragma unroll
        for (int e = 0; e < 4; e++) acc_o[i][e] = 0.f;

    uint32_t af_q[8][4];   // Q fragments, preloaded after first wait

    const float* bdb = BD + (size_t)bh * TT * TT;
    const int i_lo = i0 + wm + gr, i_hi = i_lo + 8;

    for (int t = 0; t < 8; t++){
        CP_WAIT(2);
        __syncthreads();
        if (t == 0){
            const uint32_t qf = qB + (uint32_t)((wm + arow)*68 + acol)*4;
            #pragma unroll
            for (int kk = 0; kk < 8; kk++)
                ldm4(af_q[kk], qf + (uint32_t)(kk*8)*4);
        }
        // ---- scores: S = Q @ K^T over K=64 ----
        float acc_s[16][4];
        #pragma unroll
        for (int ni = 0; ni < 16; ni++)
            #pragma unroll
            for (int e = 0; e < 4; e++) acc_s[ni][e] = 0.f;
        const uint32_t kf = kB + (uint32_t)((t & 1)*8704 + brow*68 + bcol)*4;
        #pragma unroll
        for (int kk = 0; kk < 8; kk++){
            #pragma unroll
            for (int p = 0; p < 8; p++){
                uint32_t q[4];
                ldm4(q, kf + (uint32_t)(p*16*68 + kk*8)*4);
                mma8(acc_s[2*p],     af_q[kk], q);
                mma8(acc_s[2*p + 1], af_q[kk], q + 2);
            }
        }
        // ---- rel-shift BD add + scale + online softmax ----
        const int j0 = t * 128;
        float smax_lo = -1e30f, smax_hi = -1e30f;
        #pragma unroll
        for (int ni = 0; ni < 16; ni++){
            #pragma unroll
            for (int e = 0; e < 4; e++){
                const int i = (e < 2) ? i_lo : i_hi;
                const int j = j0 + ni*8 + 2*tg + (e & 1);
                const int d = j - i;
                float bd;
                if (d <= 0)      bd = bdb[(size_t)i*TT + d + (TT - 1)];
                else if (d == 1) bd = 0.f;
                else             bd = bdb[(size_t)(i+1)*TT + d - 2];
                const float v = (acc_s[ni][e] + bd) * 0.125f;
                acc_s[ni][e] = v;
                if (e < 2) smax_lo = fmaxf(smax_lo, v);
                else       smax_hi = fmaxf(smax_hi, v);
            }
        }
        smax_lo = fmaxf(smax_lo, __shfl_xor_sync(0xffffffffu, smax_lo, 1));
        smax_lo = fmaxf(smax_lo, __shfl_xor_sync(0xffffffffu, smax_lo, 2));
        smax_hi = fmaxf(smax_hi, __shfl_xor_sync(0xffffffffu, smax_hi, 1));
        smax_hi = fmaxf(smax_hi, __shfl_xor_sync(0xffffffffu, smax_hi, 2));
        const float mn_lo = fmaxf(m_lo, smax_lo);
        const float mn_hi = fmaxf(m_hi, smax_hi);
        const float corr_lo = __expf(m_lo - mn_lo);
        const float corr_hi = __expf(m_hi - mn_hi);
        m_lo = mn_lo; m_hi = mn_hi;
        float ls_lo = 0.f, ls_hi = 0.f;
        #pragma unroll
        for (int ni = 0; ni < 16; ni++){
            float p0 = __expf(acc_s[ni][0] - mn_lo);
            float p1 = __expf(acc_s[ni][1] - mn_lo);
            float p2 = __expf(acc_s[ni][2] - mn_hi);
            float p3 = __expf(acc_s[ni][3] - mn_hi);
            ls_lo += p0 + p1; ls_hi += p2 + p3;
            float2 lo = { roundtf(p0), roundtf(p1) };
            float2 hi = { roundtf(p2), roundtf(p3) };
            *(float2*)(Ps + (wm + gr)*132 + ni*8 + 2*tg)     = lo;
            *(float2*)(Ps + (wm + gr + 8)*132 + ni*8 + 2*tg) = hi;
        }
        l_lo = l_lo * corr_lo + ls_lo;
        l_hi = l_hi * corr_hi + ls_hi;
        #pragma unroll
        for (int ni = 0; ni < 8; ni++){
            acc_o[ni][0] *= corr_lo; acc_o[ni][1] *= corr_lo;
            acc_o[ni][2] *= corr_hi; acc_o[ni][3] *= corr_hi;
        }
        __syncwarp();
        CP_WAIT(1);
        __syncthreads();
        // ---- PV: O += P @ V^T over K=128 ----
        const uint32_t pf = pB + (uint32_t)((wm + arow)*132 + acol)*4;
        const uint32_t vf = vB + (uint32_t)(brow*132 + bcol)*4;
        #pragma unroll
        for (int kk = 0; kk < 16; kk++){
            uint32_t af[4];
            ldm4(af, pf + (uint32_t)(kk*8)*4);
            #pragma unroll
            for (int p = 0; p < 4; p++){
                uint32_t q[4];
                ldm4(q, vf + (uint32_t)(p*16*132 + kk*8)*4);
                mma8(acc_o[2*p],     af, q);
                mma8(acc_o[2*p + 1], af, q + 2);
            }
        }
        __syncthreads();
        issueV(t + 1);        CP_COMMIT();
        issueK(t & 1, t + 2); CP_COMMIT();
    }

    // final: normalize rows, round, store
    l_lo += __shfl_xor_sync(0xffffffffu, l_lo, 1);
    l_lo += __shfl_xor_sync(0xffffffffu, l_lo, 2);
    l_hi += __shfl_xor_sync(0xffffffffu, l_hi, 1);
    l_hi += __shfl_xor_sync(0xffffffffu, l_hi, 2);
    const float inv_lo = 1.0f / l_lo, inv_hi = 1.0f / l_hi;
    float* out_lo = attn + ((size_t)i_lo*BB + b)*DD + h*DHD;
    float* out_hi = attn + ((size_t)i_hi*BB + b)*DD + h*DHD;
    #pragma unroll
    for (int ni = 0; ni < 8; ni++){
        const int c = ni*8 + 2*tg;
        float2 lo = { roundtf(acc_o[ni][0]*inv_lo), roundtf(acc_o[ni][1]*inv_lo) };
        float2 hi = { roundtf(acc_o[ni][2]*inv_hi), roundtf(acc_o[ni][3]*inv_hi) };
        *(float2*)(out_lo + c) = lo;
        *(float2*)(out_hi + c) = hi;
    }
}

// ---------------------------------------------------------------------------
// LayerNorm (tf32-rounded output)
// ---------------------------------------------------------------------------
__global__ __launch_bounds__(256) void ln_kernel(
    const float* __restrict__ x, const float* __restrict__ wp,
    const float* __restrict__ bparam, float* __restrict__ out)
{
    const int row = blockIdx.x;
    const int tid = threadIdx.x;
    const float4* xr = reinterpret_cast<const float4*>(x + (size_t)row * DD);
    float4 v = xr[tid];
    float s  = v.x + v.y + v.z + v.w;
    float sq = v.x*v.x + v.y*v.y + v.z*v.z + v.w*v.w;
    #pragma unroll
    for (int o = 16; o > 0; o >>= 1) {
        s  += __shfl_xor_sync(0xffffffffu, s,  o);
        sq += __shfl_xor_sync(0xffffffffu, sq, o);
    }
    __shared__ float ss[8], ssq[8];
    if ((tid & 31) == 0) { ss[tid >> 5] = s; ssq[tid >> 5] = sq; }
    __syncthreads();
    float S = 0.f, SQ = 0.f;
    #pragma unroll
    for (int i = 0; i < 8; i++) { S += ss[i]; SQ += ssq[i]; }
    const float mean = S * (1.0f / DD);
    const float var  = SQ * (1.0f / DD) - mean * mean;
    const float rstd = rsqrtf(var + 1e-5f);
    const float4 wv = reinterpret_cast<const float4*>(wp)[tid];
    const float4 bv = reinterpret_cast<const float4*>(bparam)[tid];
    float4 o;
    o.x = roundtf((v.x - mean) * rstd * wv.x + bv.x);
    o.y = roundtf((v.y - mean) * rstd * wv.y + bv.y);
    o.z = roundtf((v.z - mean) * rstd * wv.z + bv.z);
    o.w = roundtf((v.w - mean) * rstd * wv.w + bv.w);
    reinterpret_cast<float4*>(out + (size_t)row * DD)[tid] = o;
}

// ---------------------------------------------------------------------------
// Launch
// ---------------------------------------------------------------------------
extern "C" void kernel_launch(void* const* d_in, const int* in_sizes, int n_in,
                              void* d_out, int out_size)
{
    (void)in_sizes; (void)n_in; (void)out_size;
    const float* x1      = (const float*)d_in[0];
    const float* x2      = (const float*)d_in[1];
    const float* pos     = (const float*)d_in[2];
    const float* ln1_w   = (const float*)d_in[3];
    const float* ln1_b   = (const float*)d_in[4];
    const float* qkv_w   = (const float*)d_in[5];
    const float* r_w     = (const float*)d_in[6];
    const float* r_w_b   = (const float*)d_in[7];
    const float* r_r_b   = (const float*)d_in[8];
    const float* o_w     = (const float*)d_in[9];
    const float* ln2_w   = (const float*)d_in[10];
    const float* ln2_b   = (const float*)d_in[11];
    const float* ffn_w1  = (const float*)d_in[12];
    const float* ffn_b1  = (const float*)d_in[13];
    const float* ffn_w2  = (const float*)d_in[14];
    const float* ffn_b2  = (const float*)d_in[15];

    float* out = (float*)d_out;
    float* y1 = out;
    float* y2 = out + (size_t)TB * DD;

    float *p_ln, *p_qkv, *p_rk, *p_bd, *p_attn, *p_h1;
    float *p_qw, *p_qr, *p_vt, *p_posr, *p_wqkv, *p_wr, *p_wo, *p_wf1, *p_wf2;
    cudaGetSymbolAddress((void**)&p_ln,   g_ln);
    cudaGetSymbolAddress((void**)&p_qkv,  g_qkv);
    cudaGetSymbolAddress((void**)&p_rk,   g_rk);
    cudaGetSymbolAddress((void**)&p_bd,   g_bd);
    cudaGetSymbolAddress((void**)&p_attn, g_attn);
    cudaGetSymbolAddress((void**)&p_h1,   g_h1);
    cudaGetSymbolAddress((void**)&p_qw,   g_qw);
    cudaGetSymbolAddress((void**)&p_qr,   g_qr);
    cudaGetSymbolAddress((void**)&p_vt,   g_vt);
    cudaGetSymbolAddress((void**)&p_posr, g_posr);
    cudaGetSymbolAddress((void**)&p_wqkv, g_wqkv);
    cudaGetSymbolAddress((void**)&p_wr,   g_wr);
    cudaGetSymbolAddress((void**)&p_wo,   g_wo);
    cudaGetSymbolAddress((void**)&p_wf1,  g_wf1);
    cudaGetSymbolAddress((void**)&p_wf2,  g_wf2);

    const int GEMM_SMEM  = 81920;
    const int FLASH_SMEM = 205824;
    cudaFuncSetAttribute(gemm_async<0,1>, cudaFuncAttributeMaxDynamicSharedMemorySize, GEMM_SMEM);
    cudaFuncSetAttribute(gemm_async<1,1>, cudaFuncAttributeMaxDynamicSharedMemorySize, GEMM_SMEM);
    cudaFuncSetAttribute(gemm_async<2,0>, cudaFuncAttributeMaxDynamicSharedMemorySize, GEMM_SMEM);
    cudaFuncSetAttribute(gemm_async<3,0>, cudaFuncAttributeMaxDynamicSharedMemorySize, GEMM_SMEM);
    cudaFuncSetAttribute(bd_async,        cudaFuncAttributeMaxDynamicSharedMemorySize, GEMM_SMEM);
    cudaFuncSetAttribute(flash_attn,      cudaFuncAttributeMaxDynamicSharedMemorySize, FLASH_SMEM);

    // 0. all weight/pos tf32 pre-rounds in one launch
    CvtArgs ca;
    ca.src[0] = qkv_w;  ca.dst[0] = p_wqkv;
    ca.src[1] = r_w;    ca.dst[1] = p_wr;
    ca.src[2] = o_w;    ca.dst[2] = p_wo;
    ca.src[3] = ffn_w1; ca.dst[3] = p_wf1;
    ca.src[4] = ffn_w2; ca.dst[4] = p_wf2;
    ca.src[5] = pos;    ca.dst[5] = p_posr;
    cvt_multi<<<14336, 256>>>(ca);
    // 1. LN1(x2)
    ln_kernel<<<TB, 256>>>(x2, ln1_w, ln1_b, p_ln);
    // 2. qkv = ln @ qkv_w^T
    gemm_async<0,1><<<dim3(24, 64), 256, GEMM_SMEM>>>(p_ln, p_wqkv, p_qkv, 3*DD, DD, nullptr, nullptr);
    // 3. r_k = pos @ r_w^T
    gemm_async<0,1><<<dim3(8, 8), 256, GEMM_SMEM>>>(p_posr, p_wr, p_rk, DD, DD, nullptr, nullptr);
    // 4. Q prep + V transpose
    qprep_kernel<<<8192, 256>>>(p_qkv, r_w_b, r_r_b, p_qw, p_qr);
    vtrans<<<dim3(16, 128), 256>>>(p_qkv, p_vt);
    // 5. BD_pre
    bd_async<<<dim3(8, 8, BH), 256, GEMM_SMEM>>>(p_qr, p_rk, p_bd);
    // 6. fused attention
    flash_attn<<<dim3(8, BH), 256, FLASH_SMEM>>>(p_qw, p_qkv, p_vt, p_bd, p_attn);
    // 7. y1 = attn @ o_w^T + x1
    gemm_async<3,0><<<dim3(8, 64), 256, GEMM_SMEM>>>(p_attn, p_wo, y1, DD, DD, nullptr, x1);
    // 8. LN2(y1)
    ln_kernel<<<TB, 256>>>(y1, ln2_w, ln2_b, p_ln);
    // 9. h1 = relu(ln @ ffn_w1^T + b1)
    gemm_async<1,1><<<dim3(32, 64), 256, GEMM_SMEM>>>(p_ln, p_wf1, p_h1, FFD, DD, ffn_b1, nullptr);
    // 10. y2 = h1 @ ffn_w2^T + b2 + x2
    gemm_async<2,0><<<dim3(8, 64), 256, GEMM_SMEM>>>(p_h1, p_wf2, y2, DD, FFD, ffn_b2, x2);
}

// round 6
// speedup vs baseline: 1.2141x; 1.2141x over previous
#include <cuda_runtime.h>
#include <cuda_bf16.h>
#include <cstdint>
#include <cstddef>

#define TT 1024
#define BB 8
#define DD 1024
#define HH 16
#define DHD 64
#define FFD 4096
#define TB (TT*BB)
#define BH (BB*HH)

__device__ float g_ln  [(size_t)TB * DD];        // tiled
__device__ float g_qkv [(size_t)TB * 3 * DD];    // row-major
__device__ float g_rk  [(size_t)TT * DD];        // tiled
__device__ float g_bd  [(size_t)BH * TT * TT];   // row-major
__device__ float g_attn[(size_t)TB * DD];        // tiled
__device__ float g_h1  [(size_t)TB * FFD];       // tiled
__device__ float g_qw  [(size_t)BH * TT * DHD];  // row-major
__device__ float g_qr  [(size_t)BH * TT * DHD];  // tiled (rows bh*1024+i, C=64)
__device__ float g_vt  [(size_t)BH * DHD * TT];  // row-major
__device__ float g_posr[(size_t)TT * DD];        // tiled
__device__ float g_wqkv[(size_t)3 * DD * DD];    // tiled
__device__ float g_wr  [(size_t)DD * DD];        // tiled
__device__ float g_wo  [(size_t)DD * DD];        // tiled
__device__ float g_wf1 [(size_t)FFD * DD];       // tiled
__device__ float g_wf2 [(size_t)DD * FFD];       // tiled

__device__ __forceinline__ uint32_t f2tf(float x){
    uint32_t u; asm("cvt.rna.tf32.f32 %0, %1;" : "=r"(u) : "f"(x)); return u;
}
__device__ __forceinline__ float roundtf(float x){ return __uint_as_float(f2tf(x)); }
__device__ __forceinline__ void mma8(float* d, const uint32_t* a, const uint32_t* b){
    asm volatile("mma.sync.aligned.m16n8k8.row.col.f32.tf32.tf32.f32 "
        "{%0,%1,%2,%3}, {%4,%5,%6,%7}, {%8,%9}, {%0,%1,%2,%3};\n"
        : "+f"(d[0]),"+f"(d[1]),"+f"(d[2]),"+f"(d[3])
        : "r"(a[0]),"r"(a[1]),"r"(a[2]),"r"(a[3]),"r"(b[0]),"r"(b[1]));
}
__device__ __forceinline__ void ldm4(uint32_t* r, uint32_t addr){
    asm volatile("ldmatrix.sync.aligned.m8n8.x4.shared.b16 {%0,%1,%2,%3}, [%4];"
        : "=r"(r[0]),"=r"(r[1]),"=r"(r[2]),"=r"(r[3]) : "r"(addr));
}
__device__ __forceinline__ void cp16(uint32_t dst, const float* src){
    asm volatile("cp.async.cg.shared.global [%0], [%1], 16;\n" :: "r"(dst), "l"(src));
}
#define CP_COMMIT() asm volatile("cp.async.commit_group;\n")
#define CP_WAIT(n)  asm volatile("cp.async.wait_group %0;\n" :: "n"(n))
__device__ __forceinline__ uint32_t s2u(const void* p){
    return (uint32_t)__cvta_generic_to_shared(p);
}
__device__ __forceinline__ uint32_t swz(uint32_t b){ return b ^ ((b >> 3) & 0x70); }
// tiled layout: [R/128][C/32] tiles of 128x32 fl (16KB), SW128 inside
__device__ __forceinline__ float* tiled_ptr(float* base, int row, int col, int nCh){
    uint32_t byt = swz((uint32_t)((row & 127)*128 + (col & 31)*4));
    return (float*)((char*)(base + ((size_t)(row >> 7)*nCh + (col >> 5))*4096) + byt);
}
#define MBAR_INIT(a, c)  asm volatile("mbarrier.init.shared.b64 [%0], %1;" :: "r"(a), "r"(c) : "memory")
#define MBAR_EXPECT(a,t) asm volatile("mbarrier.arrive.expect_tx.shared.b64 _, [%0], %1;" :: "r"(a), "r"(t) : "memory")
#define MBAR_ARRIVE(a)   asm volatile("mbarrier.arrive.shared.b64 _, [%0];" :: "r"(a) : "memory")
__device__ __forceinline__ void mwait(uint32_t a, uint32_t p){
    asm volatile("{\n\t.reg .pred P;\n\tWL_%=:\n\t"
        "mbarrier.try_wait.parity.acquire.cta.shared::cta.b64 P, [%0], %1, 0x989680;\n\t"
        "@P bra.uni WD_%=;\n\tbra.uni WL_%=;\n\tWD_%=:\n\t}" :: "r"(a), "r"(p) : "memory");
}
__device__ __forceinline__ void mwait_rlx(uint32_t a, uint32_t p){
    asm volatile("{\n\t.reg .pred P;\n\tWL_%=:\n\t"
        "mbarrier.try_wait.parity.relaxed.cta.shared::cta.b64 P, [%0], %1, 0x989680;\n\t"
        "@P bra.uni WD_%=;\n\tbra.uni WL_%=;\n\tWD_%=:\n\t}" :: "r"(a), "r"(p) : "memory");
}
__device__ __forceinline__ void bulk16k(uint32_t dst, const float* src, uint32_t mb){
    asm volatile("cp.async.bulk.shared::cluster.global.mbarrier::complete_tx::bytes [%0], [%1], %2, [%3];"
        :: "r"(dst), "l"(src), "r"(16384), "r"(mb) : "memory");
}

// ---------------- cvt: weights+pos -> tiled tf32 ----------------
struct CvtArgs { const float* src[6]; float* dst[6]; };
__global__ __launch_bounds__(256) void cvt_multi(CvtArgs a)
{
    const int g = blockIdx.x * 256 + threadIdx.x;
    int idx = g, r = 0;
    if      (idx < 786432)  { r = 0; }
    else if (idx < 1048576) { r = 1; idx -= 786432; }
    else if (idx < 1310720) { r = 2; idx -= 1048576; }
    else if (idx < 2359296) { r = 3; idx -= 1310720; }
    else if (idx < 3407872) { r = 4; idx -= 2359296; }
    else                    { r = 5; idx -= 3407872; }
    const int lgC4 = (r == 4) ? 10 : 8;
    const int nCh  = (r == 4) ? 128 : 32;
    const int row = idx >> lgC4;
    const int col = (idx & ((1 << lgC4) - 1)) * 4;
    float4 v = reinterpret_cast<const float4*>(a.src[r])[idx];
    v.x = roundtf(v.x); v.y = roundtf(v.y); v.z = roundtf(v.z); v.w = roundtf(v.w);
    *(float4*)tiled_ptr(a.dst[r], row, col, nCh) = v;
}

// ---------------- qprep: Qw row-major, Qr tiled ----------------
__global__ __launch_bounds__(256) void qprep_kernel(
    const float* __restrict__ qkv, const float* __restrict__ rwb,
    const float* __restrict__ rrb, float* __restrict__ Qw, float* __restrict__ Qr)
{
    const int g = blockIdx.x * 256 + threadIdx.x;
    const int bh = g >> 14;
    const int rem = g & 16383;
    const int i = rem >> 4, d4 = rem & 15;
    const int b = bh >> 4, h = bh & 15;
    float4 v = *reinterpret_cast<const float4*>(qkv + ((size_t)i*BB + b)*(3*DD) + h*DHD + d4*4);
    float4 w = reinterpret_cast<const float4*>(rwb)[h*16 + d4];
    float4 r = reinterpret_cast<const float4*>(rrb)[h*16 + d4];
    float4 ow, orr;
    ow.x = roundtf(v.x + w.x); ow.y = roundtf(v.y + w.y);
    ow.z = roundtf(v.z + w.z); ow.w = roundtf(v.w + w.w);
    orr.x = roundtf(v.x + r.x); orr.y = roundtf(v.y + r.y);
    orr.z = roundtf(v.z + r.z); orr.w = roundtf(v.w + r.w);
    reinterpret_cast<float4*>(Qw)[g] = ow;
    *(float4*)tiled_ptr(Qr, bh*TT + i, d4*4, 2) = orr;
}

// ---------------- vtrans ----------------
__global__ __launch_bounds__(256) void vtrans(
    const float* __restrict__ qkv, float* __restrict__ vT)
{
    const int bh = blockIdx.y, b = bh >> 4, h = bh & 15;
    const int k0 = blockIdx.x * 64;
    __shared__ float t[64][65];
    const int tid = threadIdx.x;
    const int kr = tid >> 4;
    const int c4 = (tid & 15) * 4;
    #pragma unroll
    for (int u = 0; u < 4; u++){
        const int k = kr + u*16;
        float4 v = *(const float4*)(qkv + ((size_t)(k0 + k)*BB + b)*(3*DD) + 2*DD + h*DHD + c4);
        t[k][c4+0] = v.x; t[k][c4+1] = v.y; t[k][c4+2] = v.z; t[k][c4+3] = v.w;
    }
    __syncthreads();
    #pragma unroll
    for (int u = 0; u < 4; u++){
        const int j = kr + u*16;
        float4 o;
        o.x = t[c4+0][j]; o.y = t[c4+1][j]; o.z = t[c4+2][j]; o.w = t[c4+3][j];
        *(float4*)(vT + ((size_t)bh*DHD + j)*TT + k0 + c4) = o;
    }
}

// ---------------- bulk-DMA mainloop ----------------
// tiles: A chunk c at At + c*4096 fl, B at Bt + c*4096 (16KB each, swizzled)
// smem: [0..32) full mbars, [64..96) empty mbars, tiles at +1024
__device__ __forceinline__ void bulk_mainloop(
    const float* __restrict__ At, const float* __restrict__ Bt,
    int nCh, float* acc, char* smc)
{
    const int tid = threadIdx.x;
    const uint32_t mb = s2u(smc);
    const uint32_t tile0 = mb + 1024;
    if (tid == 0){
        #pragma unroll
        for (int s = 0; s < 4; s++){ MBAR_INIT(mb + s*8, 1); MBAR_INIT(mb + 64 + s*8, 256); }
    }
    __syncthreads();
    if (tid == 0){
        #pragma unroll
        for (int s = 0; s < 3; s++){
            if (s < nCh){
                MBAR_EXPECT(mb + s*8, 32768);
                bulk16k(tile0 + s*32768,         At + (size_t)s*4096, mb + s*8);
                bulk16k(tile0 + s*32768 + 16384, Bt + (size_t)s*4096, mb + s*8);
            }
        }
    }
    const int lane = tid & 31, w = tid >> 5;
    const int wm = (w >> 2) * 64, wn = (w & 3) * 32;
    const int arow = (lane & 7) + ((lane >> 3) & 1)*8;
    const int acol = (lane >> 4) * 4;
    const int brow = (lane & 7) + ((lane >> 4) & 1)*8;
    const int bcol = ((lane >> 3) & 1) * 4;

    for (int c = 0; c < nCh; c++){
        const int s = c & 3;
        mwait(mb + s*8, (c >> 2) & 1);
        const uint32_t aT = tile0 + s*32768;
        const uint32_t bT = aT + 16384;
        #pragma unroll
        for (int kk = 0; kk < 32; kk += 8){
            uint32_t af[4][4], bf[4][2];
            #pragma unroll
            for (int mi = 0; mi < 4; mi++)
                ldm4(af[mi], aT + swz((uint32_t)((wm + mi*16 + arow)*128 + (kk + acol)*4)));
            #pragma unroll
            for (int p = 0; p < 2; p++){
                uint32_t q[4];
                ldm4(q, bT + swz((uint32_t)((wn + p*16 + brow)*128 + (kk + bcol)*4)));
                bf[2*p][0] = q[0]; bf[2*p][1] = q[1];
                bf[2*p+1][0] = q[2]; bf[2*p+1][1] = q[3];
            }
            #pragma unroll
            for (int mi = 0; mi < 4; mi++)
                #pragma unroll
                for (int ni = 0; ni < 4; ni++)
                    mma8(acc + (mi*4 + ni)*4, af[mi], bf[ni]);
        }
        MBAR_ARRIVE(mb + 64 + s*8);
        if (tid == 0 && c + 3 < nCh){
            const int sp = (c + 3) & 3;
            if (c + 3 >= 4) mwait_rlx(mb + 64 + sp*8, ((c - 1) >> 2) & 1);
            MBAR_EXPECT(mb + sp*8, 32768);
            bulk16k(tile0 + sp*32768,         At + (size_t)(c+3)*4096, mb + sp*8);
            bulk16k(tile0 + sp*32768 + 16384, Bt + (size_t)(c+3)*4096, mb + sp*8);
        }
    }
}

// ---------------- dense GEMM (bulk) ----------------
// EPI: 0 store, 1 +bias relu, 2 +bias +res, 3 +res. ROUND: tf32 out.
// OUTT: write C tiled with outNCh chunks per row-tile.
template<int EPI, int ROUND, int OUTT>
__global__ __launch_bounds__(256, 1) void gemm_bulk(
    const float* __restrict__ A, const float* __restrict__ B, float* __restrict__ C,
    int N, int nCh, const float* __restrict__ biasN, const float* __restrict__ res,
    int outNCh)
{
    extern __shared__ char smc[];
    float acc[64];
    #pragma unroll
    for (int i = 0; i < 64; i++) acc[i] = 0.f;
    bulk_mainloop(A + (size_t)blockIdx.y * nCh * 4096,
                  B + (size_t)blockIdx.x * nCh * 4096, nCh, acc, smc);

    const int lane = threadIdx.x & 31, w = threadIdx.x >> 5;
    const int wm = (w >> 2) * 64, wn = (w & 3) * 32;
    const int gr = lane >> 2, tg = lane & 3;
    #pragma unroll
    for (int mi = 0; mi < 4; mi++)
        #pragma unroll
        for (int ni = 0; ni < 4; ni++){
            const float* a = acc + (mi*4 + ni)*4;
            const int r0 = wm + mi*16 + gr;
            const int c0 = wn + ni*8 + 2*tg;
            const int cG = blockIdx.x*128 + c0;
            #pragma unroll
            for (int half = 0; half < 2; half++){
                const int rG = blockIdx.y*128 + r0 + 8*half;
                float v0 = a[half*2 + 0], v1 = a[half*2 + 1];
                if (EPI == 1){
                    v0 += biasN[cG];     v0 = fmaxf(v0, 0.f);
                    v1 += biasN[cG + 1]; v1 = fmaxf(v1, 0.f);
                }
                if (EPI == 2){
                    v0 += biasN[cG]     + res[(size_t)rG*N + cG];
                    v1 += biasN[cG + 1] + res[(size_t)rG*N + cG + 1];
                }
                if (EPI == 3){
                    v0 += res[(size_t)rG*N + cG];
                    v1 += res[(size_t)rG*N + cG + 1];
                }
                if (ROUND){ v0 = roundtf(v0); v1 = roundtf(v1); }
                float2 o = {v0, v1};
                if (OUTT) *(float2*)tiled_ptr(C, rG, cG, outNCh) = o;
                else      *(float2*)(C + (size_t)rG*N + cG) = o;
            }
        }
}

// ---------------- BD_pre (bulk): Qr tiled x rk tiled -> row-major ----------------
__global__ __launch_bounds__(256, 1) void bd_bulk(
    const float* __restrict__ Qr, const float* __restrict__ rk, float* __restrict__ BD)
{
    extern __shared__ char smc[];
    const int bh = blockIdx.z, h = bh & 15;
    float acc[64];
    #pragma unroll
    for (int i = 0; i < 64; i++) acc[i] = 0.f;
    bulk_mainloop(Qr + (size_t)(bh*8 + blockIdx.y)*2*4096,
                  rk + (size_t)(blockIdx.x*32 + 2*h)*4096, 2, acc, smc);

    const int lane = threadIdx.x & 31, w = threadIdx.x >> 5;
    const int wm = (w >> 2) * 64, wn = (w & 3) * 32;
    float* Cb = BD + ((size_t)bh*TT + blockIdx.y*128)*TT + blockIdx.x*128;
    #pragma unroll
    for (int mi = 0; mi < 4; mi++)
        #pragma unroll
        for (int ni = 0; ni < 4; ni++){
            const float* a = acc + (mi*4 + ni)*4;
            const int r0 = wm + mi*16 + (lane >> 2);
            const int c0 = wn + ni*8 + 2*(lane & 3);
            #pragma unroll
            for (int half = 0; half < 2; half++){
                float2 o = {a[half*2], a[half*2 + 1]};
                *(float2*)(Cb + (size_t)(r0 + 8*half)*TT + c0) = o;
            }
        }
}

// ---------------- flash attention (attn output tiled) ----------------
__global__ __launch_bounds__(256, 1) void flash_attn(
    const float* __restrict__ Qw, const float* __restrict__ qkv,
    const float* __restrict__ vT, const float* __restrict__ BD,
    float* __restrict__ attn)
{
    extern __shared__ float sm[];
    float* Qs = sm;
    float* Ks = sm + 8704;
    float* Vs = sm + 26112;
    float* Ps = sm + 34560;
    const uint32_t qB = s2u(Qs), kB = s2u(Ks), vB = s2u(Vs), pB = s2u(Ps);

    const int bh = blockIdx.y, b = bh >> 4, h = bh & 15;
    const int i0 = blockIdx.x * 128;
    const int tid = threadIdx.x, lane = tid & 31, w = tid >> 5;
    const int gr = lane >> 2, tg = lane & 3;
    const int wm = w * 16;

    const int arow = (lane & 7) + ((lane >> 3) & 1)*8;
    const int acol = (lane >> 4) * 4;
    const int brow = (lane & 7) + ((lane >> 4) & 1)*8;
    const int bcol = ((lane >> 3) & 1) * 4;

    const int klr = tid >> 1, kc0 = (tid & 1) * 32;
    const int vr  = tid >> 2, vc0 = (tid & 3) * 32;

    const float* Qsrc = Qw + ((size_t)bh*TT + i0 + klr)*DHD + kc0;
    const float* Ksrc = qkv + ((size_t)klr*BB + b)*(3*DD) + DD + h*DHD + kc0;
    const size_t kRowStride = (size_t)BB*3*DD;
    const float* Vsrc = vT + ((size_t)bh*DHD + vr)*TT + vc0;

    auto issueQ = [&](){
        uint32_t d = qB + (uint32_t)(klr*68 + kc0)*4;
        #pragma unroll
        for (int u = 0; u < 8; u++) cp16(d + u*16, Qsrc + u*4);
    };
    auto issueK = [&](int slot, int jt){
        if (jt < 8){
            const float* src = Ksrc + (size_t)jt*128*kRowStride;
            uint32_t d = kB + (uint32_t)(slot*8704 + klr*68 + kc0)*4;
            #pragma unroll
            for (int u = 0; u < 8; u++) cp16(d + u*16, src + u*4);
        }
    };
    auto issueV = [&](int jt){
        if (jt < 8){
            const float* src = Vsrc + jt*128;
            uint32_t d = vB + (uint32_t)(vr*132 + vc0)*4;
            #pragma unroll
            for (int u = 0; u < 8; u++) cp16(d + u*16, src + u*4);
        }
    };

    issueQ(); issueK(0, 0); CP_COMMIT();
    issueV(0);              CP_COMMIT();
    issueK(1, 1);           CP_COMMIT();

    float m_lo = -1e30f, m_hi = -1e30f, l_lo = 0.f, l_hi = 0.f;
    float acc_o[8][4];
    #pragma unroll
    for (int i = 0; i < 8; i++)
        #pragma unroll
        for (int e = 0; e < 4; e++) acc_o[i][e] = 0.f;

    uint32_t af_q[8][4];
    const float* bdb = BD + (size_t)bh * TT * TT;
    const int i_lo = i0 + wm + gr, i_hi = i_lo + 8;

    for (int t = 0; t < 8; t++){
        CP_WAIT(2);
        __syncthreads();
        if (t == 0){
            const uint32_t qf = qB + (uint32_t)((wm + arow)*68 + acol)*4;
            #pragma unroll
            for (int kk = 0; kk < 8; kk++)
                ldm4(af_q[kk], qf + (uint32_t)(kk*8)*4);
        }
        float acc_s[16][4];
        #pragma unroll
        for (int ni = 0; ni < 16; ni++)
            #pragma unroll
            for (int e = 0; e < 4; e++) acc_s[ni][e] = 0.f;
        const uint32_t kf = kB + (uint32_t)((t & 1)*8704 + brow*68 + bcol)*4;
        #pragma unroll
        for (int kk = 0; kk < 8; kk++){
            #pragma unroll
            for (int p = 0; p < 8; p++){
                uint32_t q[4];
                ldm4(q, kf + (uint32_t)(p*16*68 + kk*8)*4);
                mma8(acc_s[2*p],     af_q[kk], q);
                mma8(acc_s[2*p + 1], af_q[kk], q + 2);
            }
        }
        const int j0 = t * 128;
        float smax_lo = -1e30f, smax_hi = -1e30f;
        #pragma unroll
        for (int ni = 0; ni < 16; ni++){
            #pragma unroll
            for (int e = 0; e < 4; e++){
                const int i = (e < 2) ? i_lo : i_hi;
                const int j = j0 + ni*8 + 2*tg + (e & 1);
                const int d = j - i;
                float bd;
                if (d <= 0)      bd = bdb[(size_t)i*TT + d + (TT - 1)];
                else if (d == 1) bd = 0.f;
                else             bd = bdb[(size_t)(i+1)*TT + d - 2];
                const float v = (acc_s[ni][e] + bd) * 0.125f;
                acc_s[ni][e] = v;
                if (e < 2) smax_lo = fmaxf(smax_lo, v);
                else       smax_hi = fmaxf(smax_hi, v);
            }
        }
        smax_lo = fmaxf(smax_lo, __shfl_xor_sync(0xffffffffu, smax_lo, 1));
        smax_lo = fmaxf(smax_lo, __shfl_xor_sync(0xffffffffu, smax_lo, 2));
        smax_hi = fmaxf(smax_hi, __shfl_xor_sync(0xffffffffu, smax_hi, 1));
        smax_hi = fmaxf(smax_hi, __shfl_xor_sync(0xffffffffu, smax_hi, 2));
        const float mn_lo = fmaxf(m_lo, smax_lo);
        const float mn_hi = fmaxf(m_hi, smax_hi);
        const float corr_lo = __expf(m_lo - mn_lo);
        const float corr_hi = __expf(m_hi - mn_hi);
        m_lo = mn_lo; m_hi = mn_hi;
        float ls_lo = 0.f, ls_hi = 0.f;
        #pragma unroll
        for (int ni = 0; ni < 16; ni++){
            float p0 = __expf(acc_s[ni][0] - mn_lo);
            float p1 = __expf(acc_s[ni][1] - mn_lo);
            float p2 = __expf(acc_s[ni][2] - mn_hi);
            float p3 = __expf(acc_s[ni][3] - mn_hi);
            ls_lo += p0 + p1; ls_hi += p2 + p3;
            float2 lo = { roundtf(p0), roundtf(p1) };
            float2 hi = { roundtf(p2), roundtf(p3) };
            *(float2*)(Ps + (wm + gr)*132 + ni*8 + 2*tg)     = lo;
            *(float2*)(Ps + (wm + gr + 8)*132 + ni*8 + 2*tg) = hi;
        }
        l_lo = l_lo * corr_lo + ls_lo;
        l_hi = l_hi * corr_hi + ls_hi;
        #pragma unroll
        for (int ni = 0; ni < 8; ni++){
            acc_o[ni][0] *= corr_lo; acc_o[ni][1] *= corr_lo;
            acc_o[ni][2] *= corr_hi; acc_o[ni][3] *= corr_hi;
        }
        __syncwarp();
        CP_WAIT(1);
        __syncthreads();
        const uint32_t pf = pB + (uint32_t)((wm + arow)*132 + acol)*4;
        const uint32_t vf = vB + (uint32_t)(brow*132 + bcol)*4;
        #pragma unroll
        for (int kk = 0; kk < 16; kk++){
            uint32_t af[4];
            ldm4(af, pf + (uint32_t)(kk*8)*4);
            #pragma unroll
            for (int p = 0; p < 4; p++){
                uint32_t q[4];
                ldm4(q, vf + (uint32_t)(p*16*132 + kk*8)*4);
                mma8(acc_o[2*p],     af, q);
                mma8(acc_o[2*p + 1], af, q + 2);
            }
        }
        __syncthreads();
        issueV(t + 1);        CP_COMMIT();
        issueK(t & 1, t + 2); CP_COMMIT();
    }

    l_lo += __shfl_xor_sync(0xffffffffu, l_lo, 1);
    l_lo += __shfl_xor_sync(0xffffffffu, l_lo, 2);
    l_hi += __shfl_xor_sync(0xffffffffu, l_hi, 1);
    l_hi += __shfl_xor_sync(0xffffffffu, l_hi, 2);
    const float inv_lo = 1.0f / l_lo, inv_hi = 1.0f / l_hi;
    #pragma unroll
    for (int ni = 0; ni < 8; ni++){
        const int c = h*DHD + ni*8 + 2*tg;
        float2 lo = { roundtf(acc_o[ni][0]*inv_lo), roundtf(acc_o[ni][1]*inv_lo) };
        float2 hi = { roundtf(acc_o[ni][2]*inv_hi), roundtf(acc_o[ni][3]*inv_hi) };
        *(float2*)tiled_ptr(attn, i_lo*BB + b, c, 32) = lo;
        *(float2*)tiled_ptr(attn, i_hi*BB + b, c, 32) = hi;
    }
}

// ---------------- LayerNorm (tiled output) ----------------
__global__ __launch_bounds__(256) void ln_kernel(
    const float* __restrict__ x, const float* __restrict__ wp,
    const float* __restrict__ bparam, float* __restrict__ out)
{
    const int row = blockIdx.x;
    const int tid = threadIdx.x;
    const float4* xr = reinterpret_cast<const float4*>(x + (size_t)row * DD);
    float4 v = xr[tid];
    float s  = v.x + v.y + v.z + v.w;
    float sq = v.x*v.x + v.y*v.y + v.z*v.z + v.w*v.w;
    #pragma unroll
    for (int o = 16; o > 0; o >>= 1) {
        s  += __shfl_xor_sync(0xffffffffu, s,  o);
        sq += __shfl_xor_sync(0xffffffffu, sq, o);
    }
    __shared__ float ss[8], ssq[8];
    if ((tid & 31) == 0) { ss[tid >> 5] = s; ssq[tid >> 5] = sq; }
    __syncthreads();
    float S = 0.f, SQ = 0.f;
    #pragma unroll
    for (int i = 0; i < 8; i++) { S += ss[i]; SQ += ssq[i]; }
    const float mean = S * (1.0f / DD);
    const float var  = SQ * (1.0f / DD) - mean * mean;
    const float rstd = rsqrtf(var + 1e-5f);
    const float4 wv = reinterpret_cast<const float4*>(wp)[tid];
    const float4 bv = reinterpret_cast<const float4*>(bparam)[tid];
    float4 o;
    o.x = roundtf((v.x - mean) * rstd * wv.x + bv.x);
    o.y = roundtf((v.y - mean) * rstd * wv.y + bv.y);
    o.z = roundtf((v.z - mean) * rstd * wv.z + bv.z);
    o.w = roundtf((v.w - mean) * rstd * wv.w + bv.w);
    *(float4*)tiled_ptr(out, row, tid*4, 32) = o;
}

// ---------------- launch ----------------
extern "C" void kernel_launch(void* const* d_in, const int* in_sizes, int n_in,
                              void* d_out, int out_size)
{
    (void)in_sizes; (void)n_in; (void)out_size;
    const float* x1      = (const float*)d_in[0];
    const float* x2      = (const float*)d_in[1];
    const float* pos     = (const float*)d_in[2];
    const float* ln1_w   = (const float*)d_in[3];
    const float* ln1_b   = (const float*)d_in[4];
    const float* qkv_w   = (const float*)d_in[5];
    const float* r_w     = (const float*)d_in[6];
    const float* r_w_b   = (const float*)d_in[7];
    const float* r_r_b   = (const float*)d_in[8];
    const float* o_w     = (const float*)d_in[9];
    const float* ln2_w   = (const float*)d_in[10];
    const float* ln2_b   = (const float*)d_in[11];
    const float* ffn_w1  = (const float*)d_in[12];
    const float* ffn_b1  = (const float*)d_in[13];
    const float* ffn_w2  = (const float*)d_in[14];
    const float* ffn_b2  = (const float*)d_in[15];

    float* out = (float*)d_out;
    float* y1 = out;
    float* y2 = out + (size_t)TB * DD;

    float *p_ln, *p_qkv, *p_rk, *p_bd, *p_attn, *p_h1;
    float *p_qw, *p_qr, *p_vt, *p_posr, *p_wqkv, *p_wr, *p_wo, *p_wf1, *p_wf2;
    cudaGetSymbolAddress((void**)&p_ln,   g_ln);
    cudaGetSymbolAddress((void**)&p_qkv,  g_qkv);
    cudaGetSymbolAddress((void**)&p_rk,   g_rk);
    cudaGetSymbolAddress((void**)&p_bd,   g_bd);
    cudaGetSymbolAddress((void**)&p_attn, g_attn);
    cudaGetSymbolAddress((void**)&p_h1,   g_h1);
    cudaGetSymbolAddress((void**)&p_qw,   g_qw);
    cudaGetSymbolAddress((void**)&p_qr,   g_qr);
    cudaGetSymbolAddress((void**)&p_vt,   g_vt);
    cudaGetSymbolAddress((void**)&p_posr, g_posr);
    cudaGetSymbolAddress((void**)&p_wqkv, g_wqkv);
    cudaGetSymbolAddress((void**)&p_wr,   g_wr);
    cudaGetSymbolAddress((void**)&p_wo,   g_wo);
    cudaGetSymbolAddress((void**)&p_wf1,  g_wf1);
    cudaGetSymbolAddress((void**)&p_wf2,  g_wf2);

    const int BULK_SMEM  = 1024 + 4*32768;   // 132096
    const int FLASH_SMEM = 205824;
    cudaFuncSetAttribute(gemm_bulk<0,1,0>, cudaFuncAttributeMaxDynamicSharedMemorySize, BULK_SMEM);
    cudaFuncSetAttribute(gemm_bulk<0,1,1>, cudaFuncAttributeMaxDynamicSharedMemorySize, BULK_SMEM);
    cudaFuncSetAttribute(gemm_bulk<1,1,1>, cudaFuncAttributeMaxDynamicSharedMemorySize, BULK_SMEM);
    cudaFuncSetAttribute(gemm_bulk<2,0,0>, cudaFuncAttributeMaxDynamicSharedMemorySize, BULK_SMEM);
    cudaFuncSetAttribute(gemm_bulk<3,0,0>, cudaFuncAttributeMaxDynamicSharedMemorySize, BULK_SMEM);
    cudaFuncSetAttribute(bd_bulk,          cudaFuncAttributeMaxDynamicSharedMemorySize, BULK_SMEM);
    cudaFuncSetAttribute(flash_attn,       cudaFuncAttributeMaxDynamicSharedMemorySize, FLASH_SMEM);

    CvtArgs ca;
    ca.src[0] = qkv_w;  ca.dst[0] = p_wqkv;
    ca.src[1] = r_w;    ca.dst[1] = p_wr;
    ca.src[2] = o_w;    ca.dst[2] = p_wo;
    ca.src[3] = ffn_w1; ca.dst[3] = p_wf1;
    ca.src[4] = ffn_w2; ca.dst[4] = p_wf2;
    ca.src[5] = pos;    ca.dst[5] = p_posr;
    cvt_multi<<<14336, 256>>>(ca);
    ln_kernel<<<TB, 256>>>(x2, ln1_w, ln1_b, p_ln);
    gemm_bulk<0,1,0><<<dim3(24, 64), 256, BULK_SMEM>>>(p_ln, p_wqkv, p_qkv, 3*DD, 32, nullptr, nullptr, 0);
    gemm_bulk<0,1,1><<<dim3(8, 8), 256, BULK_SMEM>>>(p_posr, p_wr, p_rk, DD, 32, nullptr, nullptr, 32);
    qprep_kernel<<<8192, 256>>>(p_qkv, r_w_b, r_r_b, p_qw, p_qr);
    vtrans<<<dim3(16, 128), 256>>>(p_qkv, p_vt);
    bd_bulk<<<dim3(8, 8, BH), 256, BULK_SMEM>>>(p_qr, p_rk, p_bd);
    flash_attn<<<dim3(8, BH), 256, FLASH_SMEM>>>(p_qw, p_qkv, p_vt, p_bd, p_attn);
    gemm_bulk<3,0,0><<<dim3(8, 64), 256, BULK_SMEM>>>(p_attn, p_wo, y1, DD, 32, nullptr, x1, 0);
    ln_kernel<<<TB, 256>>>(y1, ln2_w, ln2_b, p_ln);
    gemm_bulk<1,1,1><<<dim3(32, 64), 256, BULK_SMEM>>>(p_ln, p_wf1, p_h1, FFD, 32, ffn_b1, nullptr, 128);
    gemm_bulk<2,0,0><<<dim3(8, 64), 256, BULK_SMEM>>>(p_h1, p_wf2, y2, DD, 128, ffn_b2, x2, 0);
}

// round 10
// speedup vs baseline: 1.6182x; 1.3328x over previous
#include <cuda_runtime.h>
#include <cuda_fp16.h>
#include <cstdint>
#include <cstddef>

#define TT 1024
#define BB 8
#define DD 1024
#define HH 16
#define DHD 64
#define FFD 4096
#define TB (TT*BB)
#define BH (BB*HH)

// ---------------- scratch ----------------
__device__ float  g_qkv [(size_t)TB * 3 * DD];    // fp32 row-major
__device__ float  g_bd  [(size_t)BH * TT * TT];   // fp32 row-major
__device__ __half g_ln  [(size_t)TB * DD];        // h tiled nCh=16
__device__ __half g_rk  [(size_t)TT * DD];        // h tiled nCh=16
__device__ __half g_attn[(size_t)TB * DD];        // h tiled nCh=16
__device__ __half g_h1  [(size_t)TB * FFD];       // h tiled nCh=64
__device__ __half g_qw  [(size_t)BH * TT * DHD];  // h row-major
__device__ __half g_qr  [(size_t)BH * TT * DHD];  // h tiled nCh=1
__device__ __half g_kp  [(size_t)BH * TT * DHD];  // h row-major
__device__ __half g_vt  [(size_t)BH * DHD * TT];  // h row-major [bh][d][t]
__device__ __half g_posr[(size_t)TT * DD];        // h tiled
__device__ __half g_wqkv[(size_t)3 * DD * DD];    // h tiled
__device__ __half g_wr  [(size_t)DD * DD];
__device__ __half g_wo  [(size_t)DD * DD];
__device__ __half g_wf1 [(size_t)FFD * DD];
__device__ __half g_wf2 [(size_t)DD * FFD];       // h tiled nCh=64

// ---------------- helpers ----------------
__device__ __forceinline__ void mma16(float* d, const uint32_t* a, const uint32_t* b){
    asm volatile("mma.sync.aligned.m16n8k16.row.col.f32.f16.f16.f32 "
        "{%0,%1,%2,%3}, {%4,%5,%6,%7}, {%8,%9}, {%0,%1,%2,%3};\n"
        : "+f"(d[0]),"+f"(d[1]),"+f"(d[2]),"+f"(d[3])
        : "r"(a[0]),"r"(a[1]),"r"(a[2]),"r"(a[3]),"r"(b[0]),"r"(b[1]));
}
__device__ __forceinline__ void ldm4(uint32_t* r, uint32_t addr){
    asm volatile("ldmatrix.sync.aligned.m8n8.x4.shared.b16 {%0,%1,%2,%3}, [%4];"
        : "=r"(r[0]),"=r"(r[1]),"=r"(r[2]),"=r"(r[3]) : "r"(addr));
}
__device__ __forceinline__ void cp16(uint32_t dst, const void* src){
    asm volatile("cp.async.cg.shared.global [%0], [%1], 16;\n" :: "r"(dst), "l"(src));
}
#define CP_COMMIT() asm volatile("cp.async.commit_group;\n")
#define CP_WAIT(n)  asm volatile("cp.async.wait_group %0;\n" :: "n"(n))
__device__ __forceinline__ uint32_t s2u(const void* p){
    return (uint32_t)__cvta_generic_to_shared(p);
}
__device__ __forceinline__ uint32_t swz(uint32_t b){ return b ^ ((b >> 3) & 0x70); }
// half tiled layout: [R/128][C/64] tiles of 128 rows x 64 halfs (16KB), SW128
__device__ __forceinline__ __half* tiled_h(__half* base, int row, int col, int nCh){
    uint32_t byt = swz((uint32_t)((row & 127)*128 + (col & 63)*2));
    return (__half*)((char*)(base + ((size_t)(row >> 7)*nCh + (col >> 6))*8192) + byt);
}
#define MBAR_INIT(a, c)  asm volatile("mbarrier.init.shared.b64 [%0], %1;" :: "r"(a), "r"(c) : "memory")
#define MBAR_EXPECT(a,t) asm volatile("mbarrier.arrive.expect_tx.shared.b64 _, [%0], %1;" :: "r"(a), "r"(t) : "memory")
#define MBAR_ARRIVE(a)   asm volatile("mbarrier.arrive.shared.b64 _, [%0];" :: "r"(a) : "memory")
__device__ __forceinline__ void mwait(uint32_t a, uint32_t p){
    asm volatile("{\n\t.reg .pred P;\n\tWL_%=:\n\t"
        "mbarrier.try_wait.parity.acquire.cta.shared::cta.b64 P, [%0], %1, 0x989680;\n\t"
        "@P bra.uni WD_%=;\n\tbra.uni WL_%=;\n\tWD_%=:\n\t}" :: "r"(a), "r"(p) : "memory");
}
__device__ __forceinline__ void mwait_rlx(uint32_t a, uint32_t p){
    asm volatile("{\n\t.reg .pred P;\n\tWL_%=:\n\t"
        "mbarrier.try_wait.parity.relaxed.cta.shared::cta.b64 P, [%0], %1, 0x989680;\n\t"
        "@P bra.uni WD_%=;\n\tbra.uni WL_%=;\n\tWD_%=:\n\t}" :: "r"(a), "r"(p) : "memory");
}
__device__ __forceinline__ void bulk16k(uint32_t dst, const void* src, uint32_t mb){
    asm volatile("cp.async.bulk.shared::cluster.global.mbarrier::complete_tx::bytes [%0], [%1], %2, [%3];"
        :: "r"(dst), "l"(src), "r"(16384), "r"(mb) : "memory");
}

// ---------------- cvt: weights+pos fp32 -> fp16 tiled ----------------
struct CvtArgs { const float* src[6]; __half* dst[6]; };
__global__ __launch_bounds__(256) void cvt_multi(CvtArgs a)
{
    const int g = blockIdx.x * 256 + threadIdx.x;
    int idx = g, r = 0;
    if      (idx < 786432)  { r = 0; }
    else if (idx < 1048576) { r = 1; idx -= 786432; }
    else if (idx < 1310720) { r = 2; idx -= 1048576; }
    else if (idx < 2359296) { r = 3; idx -= 1310720; }
    else if (idx < 3407872) { r = 4; idx -= 2359296; }
    else                    { r = 5; idx -= 3407872; }
    const int lgC4 = (r == 4) ? 10 : 8;
    const int nCh  = (r == 4) ? 64 : 16;
    const int row = idx >> lgC4;
    const int col = (idx & ((1 << lgC4) - 1)) * 4;
    float4 v = reinterpret_cast<const float4*>(a.src[r])[idx];
    __half* p = tiled_h(a.dst[r], row, col, nCh);
    *(__half2*)p       = __floats2half2_rn(v.x, v.y);
    *(__half2*)(p + 2) = __floats2half2_rn(v.z, v.w);
}

// ---------------- qkprep: Qw/Kp rm fp16, Qr tiled fp16 ----------------
__global__ __launch_bounds__(256) void qkprep_kernel(
    const float* __restrict__ qkv, const float* __restrict__ rwb,
    const float* __restrict__ rrb, __half* __restrict__ Qw,
    __half* __restrict__ Qr, __half* __restrict__ Kp)
{
    const int g = blockIdx.x * 256 + threadIdx.x;
    const int bh = g >> 14;
    const int rem = g & 16383;
    const int i = rem >> 4, d4 = rem & 15;
    const int b = bh >> 4, h = bh & 15;
    const size_t base = ((size_t)i*BB + b)*(3*DD) + h*DHD + d4*4;
    float4 q = *reinterpret_cast<const float4*>(qkv + base);
    float4 k = *reinterpret_cast<const float4*>(qkv + base + DD);
    float4 w = reinterpret_cast<const float4*>(rwb)[h*16 + d4];
    float4 r = reinterpret_cast<const float4*>(rrb)[h*16 + d4];
    const size_t ro = ((size_t)bh*TT + i)*DHD + d4*4;
    *(__half2*)(Qw + ro)     = __floats2half2_rn(q.x + w.x, q.y + w.y);
    *(__half2*)(Qw + ro + 2) = __floats2half2_rn(q.z + w.z, q.w + w.w);
    *(__half2*)(Kp + ro)     = __floats2half2_rn(k.x, k.y);
    *(__half2*)(Kp + ro + 2) = __floats2half2_rn(k.z, k.w);
    __half* p = tiled_h(Qr, bh*TT + i, d4*4, 1);
    *(__half2*)p       = __floats2half2_rn(q.x + r.x, q.y + r.y);
    *(__half2*)(p + 2) = __floats2half2_rn(q.z + r.z, q.w + r.w);
}

// ---------------- vtrans -> fp16 [bh][d][t] ----------------
__global__ __launch_bounds__(256) void vtrans(
    const float* __restrict__ qkv, __half* __restrict__ vT)
{
    const int bh = blockIdx.y, b = bh >> 4, h = bh & 15;
    const int k0 = blockIdx.x * 64;
    __shared__ float t[64][65];
    const int tid = threadIdx.x;
    const int kr = tid >> 4;
    const int c4 = (tid & 15) * 4;
    #pragma unroll
    for (int u = 0; u < 4; u++){
        const int k = kr + u*16;
        float4 v = *(const float4*)(qkv + ((size_t)(k0 + k)*BB + b)*(3*DD) + 2*DD + h*DHD + c4);
        t[k][c4+0] = v.x; t[k][c4+1] = v.y; t[k][c4+2] = v.z; t[k][c4+3] = v.w;
    }
    __syncthreads();
    #pragma unroll
    for (int u = 0; u < 4; u++){
        const int j = kr + u*16;
        __half* o = vT + ((size_t)bh*DHD + j)*TT + k0 + c4;
        *(__half2*)o       = __floats2half2_rn(t[c4+0][j], t[c4+1][j]);
        *(__half2*)(o + 2) = __floats2half2_rn(t[c4+2][j], t[c4+3][j]);
    }
}

// ---------------- fp16 bulk-DMA mainloop ----------------
__device__ __forceinline__ void h_mainloop(
    const __half* __restrict__ At, const __half* __restrict__ Bt,
    int nCh, float* acc, char* smc)
{
    const int tid = threadIdx.x;
    const uint32_t mb = s2u(smc);
    const uint32_t tile0 = mb + 1024;
    if (tid == 0){
        #pragma unroll
        for (int s = 0; s < 4; s++){ MBAR_INIT(mb + s*8, 1); MBAR_INIT(mb + 64 + s*8, 256); }
    }
    __syncthreads();
    if (tid == 0){
        #pragma unroll
        for (int s = 0; s < 3; s++){
            if (s < nCh){
                MBAR_EXPECT(mb + s*8, 32768);
                bulk16k(tile0 + s*32768,         At + (size_t)s*8192, mb + s*8);
                bulk16k(tile0 + s*32768 + 16384, Bt + (size_t)s*8192, mb + s*8);
            }
        }
    }
    const int lane = tid & 31, w = tid >> 5;
    const int wm = (w >> 2) * 64, wn = (w & 3) * 32;
    const int arow = (lane & 7) + ((lane >> 3) & 1)*8;
    const int aoff = (lane >> 4) * 16;           // bytes (8 halfs)
    const int brow = (lane & 7) + ((lane >> 4) & 1)*8;
    const int boff = ((lane >> 3) & 1) * 16;     // bytes

    for (int c = 0; c < nCh; c++){
        const int s = c & 3;
        mwait(mb + s*8, (c >> 2) & 1);
        const uint32_t aT = tile0 + s*32768, bT = aT + 16384;
        #pragma unroll
        for (int kk = 0; kk < 4; kk++){          // 4 x k16
            uint32_t af[4][4], bf[4][2];
            #pragma unroll
            for (int mi = 0; mi < 4; mi++)
                ldm4(af[mi], aT + swz((uint32_t)((wm + mi*16 + arow)*128 + kk*32 + aoff)));
            #pragma unroll
            for (int p = 0; p < 2; p++){
                uint32_t q[4];
                ldm4(q, bT + swz((uint32_t)((wn + p*16 + brow)*128 + kk*32 + boff)));
                bf[2*p][0] = q[0]; bf[2*p][1] = q[1];
                bf[2*p+1][0] = q[2]; bf[2*p+1][1] = q[3];
            }
            #pragma unroll
            for (int mi = 0; mi < 4; mi++)
                #pragma unroll
                for (int ni = 0; ni < 4; ni++)
                    mma16(acc + (mi*4 + ni)*4, af[mi], bf[ni]);
        }
        MBAR_ARRIVE(mb + 64 + s*8);
        if (tid == 0 && c + 3 < nCh){
            const int sp = (c + 3) & 3;
            if (c + 3 >= 4) mwait_rlx(mb + 64 + sp*8, ((c - 1) >> 2) & 1);
            MBAR_EXPECT(mb + sp*8, 32768);
            bulk16k(tile0 + sp*32768,         At + (size_t)(c+3)*8192, mb + sp*8);
            bulk16k(tile0 + sp*32768 + 16384, Bt + (size_t)(c+3)*8192, mb + sp*8);
        }
    }
}

// ---------------- dense GEMM (fp16 in, fp32 or fp16 out) ----------------
template<int EPI, int OUTH>
__global__ __launch_bounds__(256, 1) void gemm_h(
    const __half* __restrict__ A, const __half* __restrict__ B, void* __restrict__ C,
    int N, int nCh, const float* __restrict__ biasN, const float* __restrict__ res,
    int outNCh)
{
    extern __shared__ char smc[];
    float acc[64];
    #pragma unroll
    for (int i = 0; i < 64; i++) acc[i] = 0.f;
    h_mainloop(A + (size_t)blockIdx.y * nCh * 8192,
               B + (size_t)blockIdx.x * nCh * 8192, nCh, acc, smc);

    const int lane = threadIdx.x & 31, w = threadIdx.x >> 5;
    const int wm = (w >> 2) * 64, wn = (w & 3) * 32;
    const int gr = lane >> 2, tg = lane & 3;
    #pragma unroll
    for (int mi = 0; mi < 4; mi++)
        #pragma unroll
        for (int ni = 0; ni < 4; ni++){
            const float* a = acc + (mi*4 + ni)*4;
            const int r0 = wm + mi*16 + gr;
            const int c0 = wn + ni*8 + 2*tg;
            const int cG = blockIdx.x*128 + c0;
            #pragma unroll
            for (int half = 0; half < 2; half++){
                const int rG = blockIdx.y*128 + r0 + 8*half;
                float v0 = a[half*2 + 0], v1 = a[half*2 + 1];
                if (EPI == 1){
                    v0 += biasN[cG];     v0 = fmaxf(v0, 0.f);
                    v1 += biasN[cG + 1]; v1 = fmaxf(v1, 0.f);
                }
                if (EPI == 2){
                    v0 += biasN[cG]     + res[(size_t)rG*N + cG];
                    v1 += biasN[cG + 1] + res[(size_t)rG*N + cG + 1];
                }
                if (EPI == 3){
                    v0 += res[(size_t)rG*N + cG];
                    v1 += res[(size_t)rG*N + cG + 1];
                }
                if (OUTH){
                    *(__half2*)tiled_h((__half*)C, rG, cG, outNCh) = __floats2half2_rn(v0, v1);
                } else {
                    float2 o = {v0, v1};
                    *(float2*)((float*)C + (size_t)rG*N + cG) = o;
                }
            }
        }
}

// ---------------- BD_pre (fp16 mainloop, fp32 rm out), nCh=1 ----------------
__global__ __launch_bounds__(256, 1) void bd_h(
    const __half* __restrict__ Qr, const __half* __restrict__ rk, float* __restrict__ BD)
{
    extern __shared__ char smc[];
    const int bh = blockIdx.z, h = bh & 15;
    float acc[64];
    #pragma unroll
    for (int i = 0; i < 64; i++) acc[i] = 0.f;
    h_mainloop(Qr + (size_t)(bh*8 + blockIdx.y)*8192,
               rk + (size_t)(blockIdx.x*16 + h)*8192, 1, acc, smc);

    const int lane = threadIdx.x & 31, w = threadIdx.x >> 5;
    const int wm = (w >> 2) * 64, wn = (w & 3) * 32;
    float* Cb = BD + ((size_t)bh*TT + blockIdx.y*128)*TT + blockIdx.x*128;
    #pragma unroll
    for (int mi = 0; mi < 4; mi++)
        #pragma unroll
        for (int ni = 0; ni < 4; ni++){
            const float* a = acc + (mi*4 + ni)*4;
            const int r0 = wm + mi*16 + (lane >> 2);
            const int c0 = wn + ni*8 + 2*(lane & 3);
            #pragma unroll
            for (int half = 0; half < 2; half++){
                float2 o = {a[half*2], a[half*2 + 1]};
                *(float2*)(Cb + (size_t)(r0 + 8*half)*TT + c0) = o;
            }
        }
}

// ---------------- flash attention (fp16) ----------------
__global__ __launch_bounds__(256, 1) void flash_attn(
    const __half* __restrict__ Qw, const __half* __restrict__ Kp,
    const __half* __restrict__ vT, const float* __restrict__ BD,
    __half* __restrict__ attn)
{
    extern __shared__ __half smh[];
    __half* Qs = smh;
    __half* Ks = smh + 9216;
    __half* Vs = smh + 27648;
    __half* Ps = smh + 36352;
    const uint32_t qB = s2u(Qs), kB = s2u(Ks), vB = s2u(Vs), pB = s2u(Ps);

    const int bh = blockIdx.y, b = bh >> 4, h = bh & 15;
    const int i0 = blockIdx.x * 128;
    const int tid = threadIdx.x, lane = tid & 31, w = tid >> 5;
    const int gr = lane >> 2, tg = lane & 3;
    const int wm = w * 16;

    const int arow = (lane & 7) + ((lane >> 3) & 1)*8;
    const int aoff = (lane >> 4) * 16;           // bytes
    const int brow = (lane & 7) + ((lane >> 4) & 1)*8;
    const int boff = ((lane >> 3) & 1) * 16;     // bytes

    const int klr = tid >> 1, kc = (tid & 1) * 32;
    const int vr  = tid >> 2, vc = (tid & 3) * 32;

    const __half* Qsrc = Qw + ((size_t)bh*TT + i0 + klr)*DHD + kc;
    const __half* Ksrc = Kp + ((size_t)bh*TT + klr)*DHD + kc;
    const __half* Vsrc = vT + ((size_t)bh*DHD + vr)*TT + vc;

    auto issueQ = [&](){
        uint32_t d = qB + (uint32_t)(klr*72 + kc)*2;
        #pragma unroll
        for (int u = 0; u < 4; u++) cp16(d + u*16, Qsrc + u*8);
    };
    auto issueK = [&](int slot, int jt){
        if (jt < 8){
            const __half* src = Ksrc + (size_t)jt*128*DHD;
            uint32_t d = kB + (uint32_t)(slot*9216 + klr*72 + kc)*2;
            #pragma unroll
            for (int u = 0; u < 4; u++) cp16(d + u*16, src + u*8);
        }
    };
    auto issueV = [&](int jt){
        if (jt < 8){
            const __half* src = Vsrc + jt*128;
            uint32_t d = vB + (uint32_t)(vr*136 + vc)*2;
            #pragma unroll
            for (int u = 0; u < 4; u++) cp16(d + u*16, src + u*8);
        }
    };

    issueQ(); issueK(0, 0); CP_COMMIT();
    issueV(0);              CP_COMMIT();
    issueK(1, 1);           CP_COMMIT();

    float m_lo = -1e30f, m_hi = -1e30f, l_lo = 0.f, l_hi = 0.f;
    float acc_o[8][4];
    #pragma unroll
    for (int i = 0; i < 8; i++)
        #pragma unroll
        for (int e = 0; e < 4; e++) acc_o[i][e] = 0.f;

    uint32_t af_q[4][4];
    const float* bdb = BD + (size_t)bh * TT * TT;
    const int i_lo = i0 + wm + gr, i_hi = i_lo + 8;

    for (int t = 0; t < 8; t++){
        CP_WAIT(2);
        __syncthreads();
        if (t == 0){
            const uint32_t qf = qB + (uint32_t)((wm + arow)*72)*2 + aoff;
            #pragma unroll
            for (int kk = 0; kk < 4; kk++)
                ldm4(af_q[kk], qf + (uint32_t)(kk*32));
        }
        float acc_s[16][4];
        #pragma unroll
        for (int ni = 0; ni < 16; ni++)
            #pragma unroll
            for (int e = 0; e < 4; e++) acc_s[ni][e] = 0.f;
        const uint32_t kf = kB + (uint32_t)((t & 1)*9216 + brow*72)*2 + boff;
        #pragma unroll
        for (int kk = 0; kk < 4; kk++){
            #pragma unroll
            for (int p = 0; p < 8; p++){
                uint32_t q[4];
                ldm4(q, kf + (uint32_t)(p*16*144 + kk*32));
                mma16(acc_s[2*p],     af_q[kk], q);
                mma16(acc_s[2*p + 1], af_q[kk], q + 2);
            }
        }
        const int j0 = t * 128;
        float smax_lo = -1e30f, smax_hi = -1e30f;
        #pragma unroll
        for (int ni = 0; ni < 16; ni++){
            #pragma unroll
            for (int e = 0; e < 4; e++){
                const int i = (e < 2) ? i_lo : i_hi;
                const int j = j0 + ni*8 + 2*tg + (e & 1);
                const int d = j - i;
                float bd;
                if (d <= 0)      bd = bdb[(size_t)i*TT + d + (TT - 1)];
                else if (d == 1) bd = 0.f;
                else             bd = bdb[(size_t)(i+1)*TT + d - 2];
                const float v = (acc_s[ni][e] + bd) * 0.125f;
                acc_s[ni][e] = v;
                if (e < 2) smax_lo = fmaxf(smax_lo, v);
                else       smax_hi = fmaxf(smax_hi, v);
            }
        }
        smax_lo = fmaxf(smax_lo, __shfl_xor_sync(0xffffffffu, smax_lo, 1));
        smax_lo = fmaxf(smax_lo, __shfl_xor_sync(0xffffffffu, smax_lo, 2));
        smax_hi = fmaxf(smax_hi, __shfl_xor_sync(0xffffffffu, smax_hi, 1));
        smax_hi = fmaxf(smax_hi, __shfl_xor_sync(0xffffffffu, smax_hi, 2));
        const float mn_lo = fmaxf(m_lo, smax_lo);
        const float mn_hi = fmaxf(m_hi, smax_hi);
        const float corr_lo = __expf(m_lo - mn_lo);
        const float corr_hi = __expf(m_hi - mn_hi);
        m_lo = mn_lo; m_hi = mn_hi;
        float ls_lo = 0.f, ls_hi = 0.f;
        #pragma unroll
        for (int ni = 0; ni < 16; ni++){
            float p0 = __expf(acc_s[ni][0] - mn_lo);
            float p1 = __expf(acc_s[ni][1] - mn_lo);
            float p2 = __expf(acc_s[ni][2] - mn_hi);
            float p3 = __expf(acc_s[ni][3] - mn_hi);
            ls_lo += p0 + p1; ls_hi += p2 + p3;
            *(__half2*)(Ps + (wm + gr)*136 + ni*8 + 2*tg)     = __floats2half2_rn(p0, p1);
            *(__half2*)(Ps + (wm + gr + 8)*136 + ni*8 + 2*tg) = __floats2half2_rn(p2, p3);
        }
        l_lo = l_lo * corr_lo + ls_lo;
        l_hi = l_hi * corr_hi + ls_hi;
        #pragma unroll
        for (int ni = 0; ni < 8; ni++){
            acc_o[ni][0] *= corr_lo; acc_o[ni][1] *= corr_lo;
            acc_o[ni][2] *= corr_hi; acc_o[ni][3] *= corr_hi;
        }
        __syncwarp();
        CP_WAIT(1);
        __syncthreads();
        const uint32_t pf = pB + (uint32_t)((wm + arow)*136)*2 + aoff;
        const uint32_t vf = vB + (uint32_t)(brow*136)*2 + boff;
        #pragma unroll
        for (int kk = 0; kk < 8; kk++){
            uint32_t af[4];
            ldm4(af, pf + (uint32_t)(kk*32));
            #pragma unroll
            for (int p = 0; p < 4; p++){
                uint32_t q[4];
                ldm4(q, vf + (uint32_t)(p*16*272 + kk*32));
                mma16(acc_o[2*p],     af, q);
                mma16(acc_o[2*p + 1], af, q + 2);
            }
        }
        __syncthreads();
        issueV(t + 1);        CP_COMMIT();
        issueK(t & 1, t + 2); CP_COMMIT();
    }

    l_lo += __shfl_xor_sync(0xffffffffu, l_lo, 1);
    l_lo += __shfl_xor_sync(0xffffffffu, l_lo, 2);
    l_hi += __shfl_xor_sync(0xffffffffu, l_hi, 1);
    l_hi += __shfl_xor_sync(0xffffffffu, l_hi, 2);
    const float inv_lo = 1.0f / l_lo, inv_hi = 1.0f / l_hi;
    #pragma unroll
    for (int ni = 0; ni < 8; ni++){
        const int c = h*DHD + ni*8 + 2*tg;
        *(__half2*)tiled_h(attn, i_lo*BB + b, c, 16) =
            __floats2half2_rn(acc_o[ni][0]*inv_lo, acc_o[ni][1]*inv_lo);
        *(__half2*)tiled_h(attn, i_hi*BB + b, c, 16) =
            __floats2half2_rn(acc_o[ni][2]*inv_hi, acc_o[ni][3]*inv_hi);
    }
}

// ---------------- LayerNorm (fp16 tiled output) ----------------
__global__ __launch_bounds__(256) void ln_kernel(
    const float* __restrict__ x, const float* __restrict__ wp,
    const float* __restrict__ bparam, __half* __restrict__ out)
{
    const int row = blockIdx.x;
    const int tid = threadIdx.x;
    const float4* xr = reinterpret_cast<const float4*>(x + (size_t)row * DD);
    float4 v = xr[tid];
    float s  = v.x + v.y + v.z + v.w;
    float sq = v.x*v.x + v.y*v.y + v.z*v.z + v.w*v.w;
    #pragma unroll
    for (int o = 16; o > 0; o >>= 1) {
        s  += __shfl_xor_sync(0xffffffffu, s,  o);
        sq += __shfl_xor_sync(0xffffffffu, sq, o);
    }
    __shared__ float ss[8], ssq[8];
    if ((tid & 31) == 0) { ss[tid >> 5] = s; ssq[tid >> 5] = sq; }
    __syncthreads();
    float S = 0.f, SQ = 0.f;
    #pragma unroll
    for (int i = 0; i < 8; i++) { S += ss[i]; SQ += ssq[i]; }
    const float mean = S * (1.0f / DD);
    const float var  = SQ * (1.0f / DD) - mean * mean;
    const float rstd = rsqrtf(var + 1e-5f);
    const float4 wv = reinterpret_cast<const float4*>(wp)[tid];
    const float4 bv = reinterpret_cast<const float4*>(bparam)[tid];
    __half* p = tiled_h(out, row, tid*4, 16);
    *(__half2*)p = __floats2half2_rn((v.x - mean)*rstd*wv.x + bv.x,
                                     (v.y - mean)*rstd*wv.y + bv.y);
    *(__half2*)(p + 2) = __floats2half2_rn((v.z - mean)*rstd*wv.z + bv.z,
                                           (v.w - mean)*rstd*wv.w + bv.w);
}

// ---------------- launch ----------------
extern "C" void kernel_launch(void* const* d_in, const int* in_sizes, int n_in,
                              void* d_out, int out_size)
{
    (void)in_sizes; (void)n_in; (void)out_size;
    const float* x1      = (const float*)d_in[0];
    const float* x2      = (const float*)d_in[1];
    const float* pos     = (const float*)d_in[2];
    const float* ln1_w   = (const float*)d_in[3];
    const float* ln1_b   = (const float*)d_in[4];
    const float* qkv_w   = (const float*)d_in[5];
    const float* r_w     = (const float*)d_in[6];
    const float* r_w_b   = (const float*)d_in[7];
    const float* r_r_b   = (const float*)d_in[8];
    const float* o_w     = (const float*)d_in[9];
    const float* ln2_w   = (const float*)d_in[10];
    const float* ln2_b   = (const float*)d_in[11];
    const float* ffn_w1  = (const float*)d_in[12];
    const float* ffn_b1  = (const float*)d_in[13];
    const float* ffn_w2  = (const float*)d_in[14];
    const float* ffn_b2  = (const float*)d_in[15];

    float* out = (float*)d_out;
    float* y1 = out;
    float* y2 = out + (size_t)TB * DD;

    float *p_qkv, *p_bd;
    __half *p_ln, *p_rk, *p_attn, *p_h1, *p_qw, *p_qr, *p_kp, *p_vt, *p_posr;
    __half *p_wqkv, *p_wr, *p_wo, *p_wf1, *p_wf2;
    cudaGetSymbolAddress((void**)&p_qkv,  g_qkv);
    cudaGetSymbolAddress((void**)&p_bd,   g_bd);
    cudaGetSymbolAddress((void**)&p_ln,   g_ln);
    cudaGetSymbolAddress((void**)&p_rk,   g_rk);
    cudaGetSymbolAddress((void**)&p_attn, g_attn);
    cudaGetSymbolAddress((void**)&p_h1,   g_h1);
    cudaGetSymbolAddress((void**)&p_qw,   g_qw);
    cudaGetSymbolAddress((void**)&p_qr,   g_qr);
    cudaGetSymbolAddress((void**)&p_kp,   g_kp);
    cudaGetSymbolAddress((void**)&p_vt,   g_vt);
    cudaGetSymbolAddress((void**)&p_posr, g_posr);
    cudaGetSymbolAddress((void**)&p_wqkv, g_wqkv);
    cudaGetSymbolAddress((void**)&p_wr,   g_wr);
    cudaGetSymbolAddress((void**)&p_wo,   g_wo);
    cudaGetSymbolAddress((void**)&p_wf1,  g_wf1);
    cudaGetSymbolAddress((void**)&p_wf2,  g_wf2);

    const int GH_SMEM    = 1024 + 4*32768;   // 132096
    const int BD_SMEM    = 1024 + 32768;     // 33792 (nCh=1, 1 stage used)
    const int FLASH_SMEM = 107520;
    cudaFuncSetAttribute(gemm_h<0,0>, cudaFuncAttributeMaxDynamicSharedMemorySize, GH_SMEM);
    cudaFuncSetAttribute(gemm_h<0,1>, cudaFuncAttributeMaxDynamicSharedMemorySize, GH_SMEM);
    cudaFuncSetAttribute(gemm_h<1,1>, cudaFuncAttributeMaxDynamicSharedMemorySize, GH_SMEM);
    cudaFuncSetAttribute(gemm_h<2,0>, cudaFuncAttributeMaxDynamicSharedMemorySize, GH_SMEM);
    cudaFuncSetAttribute(gemm_h<3,0>, cudaFuncAttributeMaxDynamicSharedMemorySize, GH_SMEM);
    cudaFuncSetAttribute(bd_h,        cudaFuncAttributeMaxDynamicSharedMemorySize, BD_SMEM);
    cudaFuncSetAttribute(flash_attn,  cudaFuncAttributeMaxDynamicSharedMemorySize, FLASH_SMEM);

    CvtArgs ca;
    ca.src[0] = qkv_w;  ca.dst[0] = p_wqkv;
    ca.src[1] = r_w;    ca.dst[1] = p_wr;
    ca.src[2] = o_w;    ca.dst[2] = p_wo;
    ca.src[3] = ffn_w1; ca.dst[3] = p_wf1;
    ca.src[4] = ffn_w2; ca.dst[4] = p_wf2;
    ca.src[5] = pos;    ca.dst[5] = p_posr;
    cvt_multi<<<14336, 256>>>(ca);
    // 1. LN1(x2) -> fp16 tiled
    ln_kernel<<<TB, 256>>>(x2, ln1_w, ln1_b, p_ln);
    // 2. qkv = ln @ qkv_w^T -> fp32 rm
    gemm_h<0,0><<<dim3(24, 64), 256, GH_SMEM>>>(p_ln, p_wqkv, p_qkv, 3*DD, 16, nullptr, nullptr, 0);
    // 3. r_k = pos @ r_w^T -> fp16 tiled
    gemm_h<0,1><<<dim3(8, 8), 256, GH_SMEM>>>(p_posr, p_wr, p_rk, DD, 16, nullptr, nullptr, 16);
    // 4. Q/K prep + V transpose (fp16)
    qkprep_kernel<<<8192, 256>>>(p_qkv, r_w_b, r_r_b, p_qw, p_qr, p_kp);
    vtrans<<<dim3(16, 128), 256>>>(p_qkv, p_vt);
    // 5. BD_pre
    bd_h<<<dim3(8, 8, BH), 256, BD_SMEM>>>(p_qr, p_rk, p_bd);
    // 6. fused attention -> attn fp16 tiled
    flash_attn<<<dim3(8, BH), 256, FLASH_SMEM>>>(p_qw, p_kp, p_vt, p_bd, p_attn);
    // 7. y1 = attn @ o_w^T + x1 -> fp32
    gemm_h<3,0><<<dim3(8, 64), 256, GH_SMEM>>>(p_attn, p_wo, y1, DD, 16, nullptr, x1, 0);
    // 8. LN2(y1) -> fp16 tiled
    ln_kernel<<<TB, 256>>>(y1, ln2_w, ln2_b, p_ln);
    // 9. h1 = relu(ln @ ffn_w1^T + b1) -> fp16 tiled
    gemm_h<1,1><<<dim3(32, 64), 256, GH_SMEM>>>(p_ln, p_wf1, p_h1, FFD, 16, ffn_b1, nullptr, 64);
    // 10. y2 = h1 @ ffn_w2^T + b2 + x2 -> fp32
    gemm_h<2,0><<<dim3(8, 64), 256, GH_SMEM>>>(p_h1, p_wf2, y2, DD, 64, ffn_b2, x2, 0);
}

// round 12
// speedup vs baseline: 1.7861x; 1.1038x over previous
#include <cuda_runtime.h>
#include <cuda_fp16.h>
#include <cstdint>
#include <cstddef>

#define TT 1024
#define BB 8
#define DD 1024
#define HH 16
#define DHD 64
#define FFD 4096
#define TB (TT*BB)
#define BH (BB*HH)

// ---------------- scratch ----------------
__device__ float  g_qkv [(size_t)TB * 3 * DD];    // fp32 row-major
__device__ __half g_bd  [(size_t)BH * TT * TT];   // fp16 row-major (256MB)
__device__ __half g_ln  [(size_t)TB * DD];        // h tiled nCh=16
__device__ __half g_rk  [(size_t)TT * DD];        // h tiled nCh=16
__device__ __half g_attn[(size_t)TB * DD];        // h tiled nCh=16
__device__ __half g_h1  [(size_t)TB * FFD];       // h tiled nCh=64
__device__ __half g_qw  [(size_t)BH * TT * DHD];  // h row-major
__device__ __half g_qr  [(size_t)BH * TT * DHD];  // h tiled nCh=1
__device__ __half g_kp  [(size_t)BH * TT * DHD];  // h row-major
__device__ __half g_vt  [(size_t)BH * DHD * TT];  // h row-major [bh][d][t]
__device__ __half g_posr[(size_t)TT * DD];        // h tiled
__device__ __half g_wqkv[(size_t)3 * DD * DD];    // h tiled
__device__ __half g_wr  [(size_t)DD * DD];
__device__ __half g_wo  [(size_t)DD * DD];
__device__ __half g_wf1 [(size_t)FFD * DD];
__device__ __half g_wf2 [(size_t)DD * FFD];       // h tiled nCh=64

// ---------------- helpers ----------------
__device__ __forceinline__ void mma16(float* d, const uint32_t* a, const uint32_t* b){
    asm volatile("mma.sync.aligned.m16n8k16.row.col.f32.f16.f16.f32 "
        "{%0,%1,%2,%3}, {%4,%5,%6,%7}, {%8,%9}, {%0,%1,%2,%3};\n"
        : "+f"(d[0]),"+f"(d[1]),"+f"(d[2]),"+f"(d[3])
        : "r"(a[0]),"r"(a[1]),"r"(a[2]),"r"(a[3]),"r"(b[0]),"r"(b[1]));
}
__device__ __forceinline__ void ldm4(uint32_t* r, uint32_t addr){
    asm volatile("ldmatrix.sync.aligned.m8n8.x4.shared.b16 {%0,%1,%2,%3}, [%4];"
        : "=r"(r[0]),"=r"(r[1]),"=r"(r[2]),"=r"(r[3]) : "r"(addr));
}
__device__ __forceinline__ void cp16(uint32_t dst, const void* src){
    asm volatile("cp.async.cg.shared.global [%0], [%1], 16;\n" :: "r"(dst), "l"(src));
}
#define CP_COMMIT() asm volatile("cp.async.commit_group;\n")
#define CP_WAIT(n)  asm volatile("cp.async.wait_group %0;\n" :: "n"(n))
__device__ __forceinline__ uint32_t s2u(const void* p){
    return (uint32_t)__cvta_generic_to_shared(p);
}
__device__ __forceinline__ uint32_t swz(uint32_t b){ return b ^ ((b >> 3) & 0x70); }
// half tiled layout: [R/128][C/64] tiles of 128 rows x 64 halfs (16KB), SW128
__device__ __forceinline__ __half* tiled_h(__half* base, int row, int col, int nCh){
    uint32_t byt = swz((uint32_t)((row & 127)*128 + (col & 63)*2));
    return (__half*)((char*)(base + ((size_t)(row >> 7)*nCh + (col >> 6))*8192) + byt);
}
#define MBAR_INIT(a, c)  asm volatile("mbarrier.init.shared.b64 [%0], %1;" :: "r"(a), "r"(c) : "memory")
#define MBAR_EXPECT(a,t) asm volatile("mbarrier.arrive.expect_tx.shared.b64 _, [%0], %1;" :: "r"(a), "r"(t) : "memory")
#define MBAR_ARRIVE(a)   asm volatile("mbarrier.arrive.shared.b64 _, [%0];" :: "r"(a) : "memory")
__device__ __forceinline__ void mwait(uint32_t a, uint32_t p){
    asm volatile("{\n\t.reg .pred P;\n\tWL_%=:\n\t"
        "mbarrier.try_wait.parity.acquire.cta.shared::cta.b64 P, [%0], %1, 0x989680;\n\t"
        "@P bra.uni WD_%=;\n\tbra.uni WL_%=;\n\tWD_%=:\n\t}" :: "r"(a), "r"(p) : "memory");
}
__device__ __forceinline__ void mwait_rlx(uint32_t a, uint32_t p){
    asm volatile("{\n\t.reg .pred P;\n\tWL_%=:\n\t"
        "mbarrier.try_wait.parity.relaxed.cta.shared::cta.b64 P, [%0], %1, 0x989680;\n\t"
        "@P bra.uni WD_%=;\n\tbra.uni WL_%=;\n\tWD_%=:\n\t}" :: "r"(a), "r"(p) : "memory");
}
__device__ __forceinline__ void bulk16k(uint32_t dst, const void* src, uint32_t mb){
    asm volatile("cp.async.bulk.shared::cluster.global.mbarrier::complete_tx::bytes [%0], [%1], %2, [%3];"
        :: "r"(dst), "l"(src), "r"(16384), "r"(mb) : "memory");
}

// ---------------- cvt: weights+pos fp32 -> fp16 tiled ----------------
struct CvtArgs { const float* src[6]; __half* dst[6]; };
__global__ __launch_bounds__(256) void cvt_multi(CvtArgs a)
{
    const int g = blockIdx.x * 256 + threadIdx.x;
    int idx = g, r = 0;
    if      (idx < 786432)  { r = 0; }
    else if (idx < 1048576) { r = 1; idx -= 786432; }
    else if (idx < 1310720) { r = 2; idx -= 1048576; }
    else if (idx < 2359296) { r = 3; idx -= 1310720; }
    else if (idx < 3407872) { r = 4; idx -= 2359296; }
    else                    { r = 5; idx -= 3407872; }
    const int lgC4 = (r == 4) ? 10 : 8;
    const int nCh  = (r == 4) ? 64 : 16;
    const int row = idx >> lgC4;
    const int col = (idx & ((1 << lgC4) - 1)) * 4;
    float4 v = reinterpret_cast<const float4*>(a.src[r])[idx];
    __half* p = tiled_h(a.dst[r], row, col, nCh);
    *(__half2*)p       = __floats2half2_rn(v.x, v.y);
    *(__half2*)(p + 2) = __floats2half2_rn(v.z, v.w);
}

// ---------------- qkprep: Qw/Kp rm fp16, Qr tiled fp16 ----------------
__global__ __launch_bounds__(256) void qkprep_kernel(
    const float* __restrict__ qkv, const float* __restrict__ rwb,
    const float* __restrict__ rrb, __half* __restrict__ Qw,
    __half* __restrict__ Qr, __half* __restrict__ Kp)
{
    const int g = blockIdx.x * 256 + threadIdx.x;
    const int bh = g >> 14;
    const int rem = g & 16383;
    const int i = rem >> 4, d4 = rem & 15;
    const int b = bh >> 4, h = bh & 15;
    const size_t base = ((size_t)i*BB + b)*(3*DD) + h*DHD + d4*4;
    float4 q = *reinterpret_cast<const float4*>(qkv + base);
    float4 k = *reinterpret_cast<const float4*>(qkv + base + DD);
    float4 w = reinterpret_cast<const float4*>(rwb)[h*16 + d4];
    float4 r = reinterpret_cast<const float4*>(rrb)[h*16 + d4];
    const size_t ro = ((size_t)bh*TT + i)*DHD + d4*4;
    *(__half2*)(Qw + ro)     = __floats2half2_rn(q.x + w.x, q.y + w.y);
    *(__half2*)(Qw + ro + 2) = __floats2half2_rn(q.z + w.z, q.w + w.w);
    *(__half2*)(Kp + ro)     = __floats2half2_rn(k.x, k.y);
    *(__half2*)(Kp + ro + 2) = __floats2half2_rn(k.z, k.w);
    __half* p = tiled_h(Qr, bh*TT + i, d4*4, 1);
    *(__half2*)p       = __floats2half2_rn(q.x + r.x, q.y + r.y);
    *(__half2*)(p + 2) = __floats2half2_rn(q.z + r.z, q.w + r.w);
}

// ---------------- vtrans -> fp16 [bh][d][t] ----------------
__global__ __launch_bounds__(256) void vtrans(
    const float* __restrict__ qkv, __half* __restrict__ vT)
{
    const int bh = blockIdx.y, b = bh >> 4, h = bh & 15;
    const int k0 = blockIdx.x * 64;
    __shared__ float t[64][65];
    const int tid = threadIdx.x;
    const int kr = tid >> 4;
    const int c4 = (tid & 15) * 4;
    #pragma unroll
    for (int u = 0; u < 4; u++){
        const int k = kr + u*16;
        float4 v = *(const float4*)(qkv + ((size_t)(k0 + k)*BB + b)*(3*DD) + 2*DD + h*DHD + c4);
        t[k][c4+0] = v.x; t[k][c4+1] = v.y; t[k][c4+2] = v.z; t[k][c4+3] = v.w;
    }
    __syncthreads();
    #pragma unroll
    for (int u = 0; u < 4; u++){
        const int j = kr + u*16;
        __half* o = vT + ((size_t)bh*DHD + j)*TT + k0 + c4;
        *(__half2*)o       = __floats2half2_rn(t[c4+0][j], t[c4+1][j]);
        *(__half2*)(o + 2) = __floats2half2_rn(t[c4+2][j], t[c4+3][j]);
    }
}

// ---------------- fp16 bulk-DMA mainloop (512 threads / 16 warps) ----------------
// per chunk c (K=64 halfs): A tile 16KB at At + c*8192, B tile at Bt + c*8192
// each warp computes a 32x32 sub-tile: acc[32]
__device__ __forceinline__ void h_mainloop16(
    const __half* __restrict__ At, const __half* __restrict__ Bt,
    int nCh, float* acc, char* smc)
{
    const int tid = threadIdx.x;
    const uint32_t mb = s2u(smc);
    const uint32_t tile0 = mb + 1024;
    if (tid == 0){
        #pragma unroll
        for (int s = 0; s < 4; s++){ MBAR_INIT(mb + s*8, 1); MBAR_INIT(mb + 64 + s*8, 512); }
    }
    __syncthreads();
    if (tid == 0){
        #pragma unroll
        for (int s = 0; s < 3; s++){
            if (s < nCh){
                MBAR_EXPECT(mb + s*8, 32768);
                bulk16k(tile0 + s*32768,         At + (size_t)s*8192, mb + s*8);
                bulk16k(tile0 + s*32768 + 16384, Bt + (size_t)s*8192, mb + s*8);
            }
        }
    }
    const int lane = tid & 31, w = tid >> 5;          // w: 0..15
    const int wm = (w >> 2) * 32, wn = (w & 3) * 32;
    const int arow = (lane & 7) + ((lane >> 3) & 1)*8;
    const int aoff = (lane >> 4) * 16;                // bytes (8 halfs)
    const int brow = (lane & 7) + ((lane >> 4) & 1)*8;
    const int boff = ((lane >> 3) & 1) * 16;          // bytes

    for (int c = 0; c < nCh; c++){
        const int s = c & 3;
        mwait(mb + s*8, (c >> 2) & 1);
        const uint32_t aT = tile0 + s*32768, bT = aT + 16384;
        #pragma unroll
        for (int kk = 0; kk < 4; kk++){               // 4 x k16
            uint32_t af[2][4], bf[4][2];
            #pragma unroll
            for (int mi = 0; mi < 2; mi++)
                ldm4(af[mi], aT + swz((uint32_t)((wm + mi*16 + arow)*128 + kk*32 + aoff)));
            #pragma unroll
            for (int p = 0; p < 2; p++){
                uint32_t q[4];
                ldm4(q, bT + swz((uint32_t)((wn + p*16 + brow)*128 + kk*32 + boff)));
                bf[2*p][0] = q[0]; bf[2*p][1] = q[1];
                bf[2*p+1][0] = q[2]; bf[2*p+1][1] = q[3];
            }
            #pragma unroll
            for (int mi = 0; mi < 2; mi++)
                #pragma unroll
                for (int ni = 0; ni < 4; ni++)
                    mma16(acc + (mi*4 + ni)*4, af[mi], bf[ni]);
        }
        MBAR_ARRIVE(mb + 64 + s*8);
        if (tid == 0 && c + 3 < nCh){
            const int sp = (c + 3) & 3;
            if (c + 3 >= 4) mwait_rlx(mb + 64 + sp*8, ((c - 1) >> 2) & 1);
            MBAR_EXPECT(mb + sp*8, 32768);
            bulk16k(tile0 + sp*32768,         At + (size_t)(c+3)*8192, mb + sp*8);
            bulk16k(tile0 + sp*32768 + 16384, Bt + (size_t)(c+3)*8192, mb + sp*8);
        }
    }
}

// ---------------- dense GEMM (16 warps; fp16 in, fp32 or fp16 out) ----------------
// EPI: 0 store, 1 +bias relu, 2 +bias +res, 3 +res. OUTH: fp16 tiled out.
template<int EPI, int OUTH>
__global__ __launch_bounds__(512, 1) void gemm_h(
    const __half* __restrict__ A, const __half* __restrict__ B, void* __restrict__ C,
    int N, int nCh, const float* __restrict__ biasN, const float* __restrict__ res,
    int outNCh)
{
    extern __shared__ char smc[];
    float acc[32];
    #pragma unroll
    for (int i = 0; i < 32; i++) acc[i] = 0.f;
    h_mainloop16(A + (size_t)blockIdx.y * nCh * 8192,
                 B + (size_t)blockIdx.x * nCh * 8192, nCh, acc, smc);

    const int lane = threadIdx.x & 31, w = threadIdx.x >> 5;
    const int wm = (w >> 2) * 32, wn = (w & 3) * 32;
    const int gr = lane >> 2, tg = lane & 3;
    #pragma unroll
    for (int mi = 0; mi < 2; mi++)
        #pragma unroll
        for (int ni = 0; ni < 4; ni++){
            const float* a = acc + (mi*4 + ni)*4;
            const int r0 = wm + mi*16 + gr;
            const int c0 = wn + ni*8 + 2*tg;
            const int cG = blockIdx.x*128 + c0;
            #pragma unroll
            for (int half = 0; half < 2; half++){
                const int rG = blockIdx.y*128 + r0 + 8*half;
                float v0 = a[half*2 + 0], v1 = a[half*2 + 1];
                if (EPI == 1){
                    v0 += biasN[cG];     v0 = fmaxf(v0, 0.f);
                    v1 += biasN[cG + 1]; v1 = fmaxf(v1, 0.f);
                }
                if (EPI == 2){
                    v0 += biasN[cG]     + res[(size_t)rG*N + cG];
                    v1 += biasN[cG + 1] + res[(size_t)rG*N + cG + 1];
                }
                if (EPI == 3){
                    v0 += res[(size_t)rG*N + cG];
                    v1 += res[(size_t)rG*N + cG + 1];
                }
                if (OUTH){
                    *(__half2*)tiled_h((__half*)C, rG, cG, outNCh) = __floats2half2_rn(v0, v1);
                } else {
                    float2 o = {v0, v1};
                    *(float2*)((float*)C + (size_t)rG*N + cG) = o;
                }
            }
        }
}

// ---------------- BD_pre (16 warps, fp16 rm out), nCh=1 ----------------
__global__ __launch_bounds__(512, 1) void bd_h(
    const __half* __restrict__ Qr, const __half* __restrict__ rk, __half* __restrict__ BD)
{
    extern __shared__ char smc[];
    const int bh = blockIdx.z, h = bh & 15;
    float acc[32];
    #pragma unroll
    for (int i = 0; i < 32; i++) acc[i] = 0.f;
    h_mainloop16(Qr + (size_t)(bh*8 + blockIdx.y)*8192,
                 rk + (size_t)(blockIdx.x*16 + h)*8192, 1, acc, smc);

    const int lane = threadIdx.x & 31, w = threadIdx.x >> 5;
    const int wm = (w >> 2) * 32, wn = (w & 3) * 32;
    __half* Cb = BD + ((size_t)bh*TT + blockIdx.y*128)*TT + blockIdx.x*128;
    #pragma unroll
    for (int mi = 0; mi < 2; mi++)
        #pragma unroll
        for (int ni = 0; ni < 4; ni++){
            const float* a = acc + (mi*4 + ni)*4;
            const int r0 = wm + mi*16 + (lane >> 2);
            const int c0 = wn + ni*8 + 2*(lane & 3);
            #pragma unroll
            for (int half = 0; half < 2; half++){
                *(__half2*)(Cb + (size_t)(r0 + 8*half)*TT + c0) =
                    __floats2half2_rn(a[half*2], a[half*2 + 1]);
            }
        }
}

// ---------------- flash attention (fp16; BD read as fp16) ----------------
__global__ __launch_bounds__(256, 1) void flash_attn(
    const __half* __restrict__ Qw, const __half* __restrict__ Kp,
    const __half* __restrict__ vT, const __half* __restrict__ BD,
    __half* __restrict__ attn)
{
    extern __shared__ __half smh[];
    __half* Qs = smh;
    __half* Ks = smh + 9216;
    __half* Vs = smh + 27648;
    __half* Ps = smh + 36352;
    const uint32_t qB = s2u(Qs), kB = s2u(Ks), vB = s2u(Vs), pB = s2u(Ps);

    const int bh = blockIdx.y, b = bh >> 4, h = bh & 15;
    const int i0 = blockIdx.x * 128;
    const int tid = threadIdx.x, lane = tid & 31, w = tid >> 5;
    const int gr = lane >> 2, tg = lane & 3;
    const int wm = w * 16;

    const int arow = (lane & 7) + ((lane >> 3) & 1)*8;
    const int aoff = (lane >> 4) * 16;           // bytes
    const int brow = (lane & 7) + ((lane >> 4) & 1)*8;
    const int boff = ((lane >> 3) & 1) * 16;     // bytes

    const int klr = tid >> 1, kc = (tid & 1) * 32;
    const int vr  = tid >> 2, vc = (tid & 3) * 32;

    const __half* Qsrc = Qw + ((size_t)bh*TT + i0 + klr)*DHD + kc;
    const __half* Ksrc = Kp + ((size_t)bh*TT + klr)*DHD + kc;
    const __half* Vsrc = vT + ((size_t)bh*DHD + vr)*TT + vc;

    auto issueQ = [&](){
        uint32_t d = qB + (uint32_t)(klr*72 + kc)*2;
        #pragma unroll
        for (int u = 0; u < 4; u++) cp16(d + u*16, Qsrc + u*8);
    };
    auto issueK = [&](int slot, int jt){
        if (jt < 8){
            const __half* src = Ksrc + (size_t)jt*128*DHD;
            uint32_t d = kB + (uint32_t)(slot*9216 + klr*72 + kc)*2;
            #pragma unroll
            for (int u = 0; u < 4; u++) cp16(d + u*16, src + u*8);
        }
    };
    auto issueV = [&](int jt){
        if (jt < 8){
            const __half* src = Vsrc + jt*128;
            uint32_t d = vB + (uint32_t)(vr*136 + vc)*2;
            #pragma unroll
            for (int u = 0; u < 4; u++) cp16(d + u*16, src + u*8);
        }
    };

    issueQ(); issueK(0, 0); CP_COMMIT();
    issueV(0);              CP_COMMIT();
    issueK(1, 1);           CP_COMMIT();

    float m_lo = -1e30f, m_hi = -1e30f, l_lo = 0.f, l_hi = 0.f;
    float acc_o[8][4];
    #pragma unroll
    for (int i = 0; i < 8; i++)
        #pragma unroll
        for (int e = 0; e < 4; e++) acc_o[i][e] = 0.f;

    uint32_t af_q[4][4];
    const __half* bdb = BD + (size_t)bh * TT * TT;
    const int i_lo = i0 + wm + gr, i_hi = i_lo + 8;

    for (int t = 0; t < 8; t++){
        CP_WAIT(2);
        __syncthreads();
        if (t == 0){
            const uint32_t qf = qB + (uint32_t)((wm + arow)*72)*2 + aoff;
            #pragma unroll
            for (int kk = 0; kk < 4; kk++)
                ldm4(af_q[kk], qf + (uint32_t)(kk*32));
        }
        float acc_s[16][4];
        #pragma unroll
        for (int ni = 0; ni < 16; ni++)
            #pragma unroll
            for (int e = 0; e < 4; e++) acc_s[ni][e] = 0.f;
        const uint32_t kf = kB + (uint32_t)((t & 1)*9216 + brow*72)*2 + boff;
        #pragma unroll
        for (int kk = 0; kk < 4; kk++){
            #pragma unroll
            for (int p = 0; p < 8; p++){
                uint32_t q[4];
                ldm4(q, kf + (uint32_t)(p*16*144 + kk*32));
                mma16(acc_s[2*p],     af_q[kk], q);
                mma16(acc_s[2*p + 1], af_q[kk], q + 2);
            }
        }
        const int j0 = t * 128;
        float smax_lo = -1e30f, smax_hi = -1e30f;
        #pragma unroll
        for (int ni = 0; ni < 16; ni++){
            #pragma unroll
            for (int e = 0; e < 4; e++){
                const int i = (e < 2) ? i_lo : i_hi;
                const int j = j0 + ni*8 + 2*tg + (e & 1);
                const int d = j - i;
                float bd;
                if (d <= 0)      bd = __half2float(bdb[(size_t)i*TT + d + (TT - 1)]);
                else if (d == 1) bd = 0.f;
                else             bd = __half2float(bdb[(size_t)(i+1)*TT + d - 2]);
                const float v = (acc_s[ni][e] + bd) * 0.125f;
                acc_s[ni][e] = v;
                if (e < 2) smax_lo = fmaxf(smax_lo, v);
                else       smax_hi = fmaxf(smax_hi, v);
            }
        }
        smax_lo = fmaxf(smax_lo, __shfl_xor_sync(0xffffffffu, smax_lo, 1));
        smax_lo = fmaxf(smax_lo, __shfl_xor_sync(0xffffffffu, smax_lo, 2));
        smax_hi = fmaxf(smax_hi, __shfl_xor_sync(0xffffffffu, smax_hi, 1));
        smax_hi = fmaxf(smax_hi, __shfl_xor_sync(0xffffffffu, smax_hi, 2));
        const float mn_lo = fmaxf(m_lo, smax_lo);
        const float mn_hi = fmaxf(m_hi, smax_hi);
        const float corr_lo = __expf(m_lo - mn_lo);
        const float corr_hi = __expf(m_hi - mn_hi);
        m_lo = mn_lo; m_hi = mn_hi;
        float ls_lo = 0.f, ls_hi = 0.f;
        #pragma unroll
        for (int ni = 0; ni < 16; ni++){
            float p0 = __expf(acc_s[ni][0] - mn_lo);
            float p1 = __expf(acc_s[ni][1] - mn_lo);
            float p2 = __expf(acc_s[ni][2] - mn_hi);
            float p3 = __expf(acc_s[ni][3] - mn_hi);
            ls_lo += p0 + p1; ls_hi += p2 + p3;
            *(__half2*)(Ps + (wm + gr)*136 + ni*8 + 2*tg)     = __floats2half2_rn(p0, p1);
            *(__half2*)(Ps + (wm + gr + 8)*136 + ni*8 + 2*tg) = __floats2half2_rn(p2, p3);
        }
        l_lo = l_lo * corr_lo + ls_lo;
        l_hi = l_hi * corr_hi + ls_hi;
        #pragma unroll
        for (int ni = 0; ni < 8; ni++){
            acc_o[ni][0] *= corr_lo; acc_o[ni][1] *= corr_lo;
            acc_o[ni][2] *= corr_hi; acc_o[ni][3] *= corr_hi;
        }
        __syncwarp();
        CP_WAIT(1);
        __syncthreads();
        const uint32_t pf = pB + (uint32_t)((wm + arow)*136)*2 + aoff;
        const uint32_t vf = vB + (uint32_t)(brow*136)*2 + boff;
        #pragma unroll
        for (int kk = 0; kk < 8; kk++){
            uint32_t af[4];
            ldm4(af, pf + (uint32_t)(kk*32));
            #pragma unroll
            for (int p = 0; p < 4; p++){
                uint32_t q[4];
                ldm4(q, vf + (uint32_t)(p*16*272 + kk*32));
                mma16(acc_o[2*p],     af, q);
                mma16(acc_o[2*p + 1], af, q + 2);
            }
        }
        __syncthreads();
        issueV(t + 1);        CP_COMMIT();
        issueK(t & 1, t + 2); CP_COMMIT();
    }

    l_lo += __shfl_xor_sync(0xffffffffu, l_lo, 1);
    l_lo += __shfl_xor_sync(0xffffffffu, l_lo, 2);
    l_hi += __shfl_xor_sync(0xffffffffu, l_hi, 1);
    l_hi += __shfl_xor_sync(0xffffffffu, l_hi, 2);
    const float inv_lo = 1.0f / l_lo, inv_hi = 1.0f / l_hi;
    #pragma unroll
    for (int ni = 0; ni < 8; ni++){
        const int c = h*DHD + ni*8 + 2*tg;
        *(__half2*)tiled_h(attn, i_lo*BB + b, c, 16) =
            __floats2half2_rn(acc_o[ni][0]*inv_lo, acc_o[ni][1]*inv_lo);
        *(__half2*)tiled_h(attn, i_hi*BB + b, c, 16) =
            __floats2half2_rn(acc_o[ni][2]*inv_hi, acc_o[ni][3]*inv_hi);
    }
}

// ---------------- LayerNorm (fp16 tiled output) ----------------
__global__ __launch_bounds__(256) void ln_kernel(
    const float* __restrict__ x, const float* __restrict__ wp,
    const float* __restrict__ bparam, __half* __restrict__ out)
{
    const int row = blockIdx.x;
    const int tid = threadIdx.x;
    const float4* xr = reinterpret_cast<const float4*>(x + (size_t)row * DD);
    float4 v = xr[tid];
    float s  = v.x + v.y + v.z + v.w;
    float sq = v.x*v.x + v.y*v.y + v.z*v.z + v.w*v.w;
    #pragma unroll
    for (int o = 16; o > 0; o >>= 1) {
        s  += __shfl_xor_sync(0xffffffffu, s,  o);
        sq += __shfl_xor_sync(0xffffffffu, sq, o);
    }
    __shared__ float ss[8], ssq[8];
    if ((tid & 31) == 0) { ss[tid >> 5] = s; ssq[tid >> 5] = sq; }
    __syncthreads();
    float S = 0.f, SQ = 0.f;
    #pragma unroll
    for (int i = 0; i < 8; i++) { S += ss[i]; SQ += ssq[i]; }
    const float mean = S * (1.0f / DD);
    const float var  = SQ * (1.0f / DD) - mean * mean;
    const float rstd = rsqrtf(var + 1e-5f);
    const float4 wv = reinterpret_cast<const float4*>(wp)[tid];
    const float4 bv = reinterpret_cast<const float4*>(bparam)[tid];
    __half* p = tiled_h(out, row, tid*4, 16);
    *(__half2*)p = __floats2half2_rn((v.x - mean)*rstd*wv.x + bv.x,
                                     (v.y - mean)*rstd*wv.y + bv.y);
    *(__half2*)(p + 2) = __floats2half2_rn((v.z - mean)*rstd*wv.z + bv.z,
                                           (v.w - mean)*rstd*wv.w + bv.w);
}

// ---------------- launch ----------------
extern "C" void kernel_launch(void* const* d_in, const int* in_sizes, int n_in,
                              void* d_out, int out_size)
{
    (void)in_sizes; (void)n_in; (void)out_size;
    const float* x1      = (const float*)d_in[0];
    const float* x2      = (const float*)d_in[1];
    const float* pos     = (const float*)d_in[2];
    const float* ln1_w   = (const float*)d_in[3];
    const float* ln1_b   = (const float*)d_in[4];
    const float* qkv_w   = (const float*)d_in[5];
    const float* r_w     = (const float*)d_in[6];
    const float* r_w_b   = (const float*)d_in[7];
    const float* r_r_b   = (const float*)d_in[8];
    const float* o_w     = (const float*)d_in[9];
    const float* ln2_w   = (const float*)d_in[10];
    const float* ln2_b   = (const float*)d_in[11];
    const float* ffn_w1  = (const float*)d_in[12];
    const float* ffn_b1  = (const float*)d_in[13];
    const float* ffn_w2  = (const float*)d_in[14];
    const float* ffn_b2  = (const float*)d_in[15];

    float* out = (float*)d_out;
    float* y1 = out;
    float* y2 = out + (size_t)TB * DD;

    float *p_qkv;
    __half *p_bd, *p_ln, *p_rk, *p_attn, *p_h1, *p_qw, *p_qr, *p_kp, *p_vt, *p_posr;
    __half *p_wqkv, *p_wr, *p_wo, *p_wf1, *p_wf2;
    cudaGetSymbolAddress((void**)&p_qkv,  g_qkv);
    cudaGetSymbolAddress((void**)&p_bd,   g_bd);
    cudaGetSymbolAddress((void**)&p_ln,   g_ln);
    cudaGetSymbolAddress((void**)&p_rk,   g_rk);
    cudaGetSymbolAddress((void**)&p_attn, g_attn);
    cudaGetSymbolAddress((void**)&p_h1,   g_h1);
    cudaGetSymbolAddress((void**)&p_qw,   g_qw);
    cudaGetSymbolAddress((void**)&p_qr,   g_qr);
    cudaGetSymbolAddress((void**)&p_kp,   g_kp);
    cudaGetSymbolAddress((void**)&p_vt,   g_vt);
    cudaGetSymbolAddress((void**)&p_posr, g_posr);
    cudaGetSymbolAddress((void**)&p_wqkv, g_wqkv);
    cudaGetSymbolAddress((void**)&p_wr,   g_wr);
    cudaGetSymbolAddress((void**)&p_wo,   g_wo);
    cudaGetSymbolAddress((void**)&p_wf1,  g_wf1);
    cudaGetSymbolAddress((void**)&p_wf2,  g_wf2);

    const int GH_SMEM    = 1024 + 4*32768;   // 132096
    const int BD_SMEM    = 1024 + 32768;     // 33792 (nCh=1)
    const int FLASH_SMEM = 107520;
    cudaFuncSetAttribute(gemm_h<0,0>, cudaFuncAttributeMaxDynamicSharedMemorySize, GH_SMEM);
    cudaFuncSetAttribute(gemm_h<0,1>, cudaFuncAttributeMaxDynamicSharedMemorySize, GH_SMEM);
    cudaFuncSetAttribute(gemm_h<1,1>, cudaFuncAttributeMaxDynamicSharedMemorySize, GH_SMEM);
    cudaFuncSetAttribute(gemm_h<2,0>, cudaFuncAttributeMaxDynamicSharedMemorySize, GH_SMEM);
    cudaFuncSetAttribute(gemm_h<3,0>, cudaFuncAttributeMaxDynamicSharedMemorySize, GH_SMEM);
    cudaFuncSetAttribute(bd_h,        cudaFuncAttributeMaxDynamicSharedMemorySize, BD_SMEM);
    cudaFuncSetAttribute(flash_attn,  cudaFuncAttributeMaxDynamicSharedMemorySize, FLASH_SMEM);

    CvtArgs ca;
    ca.src[0] = qkv_w;  ca.dst[0] = p_wqkv;
    ca.src[1] = r_w;    ca.dst[1] = p_wr;
    ca.src[2] = o_w;    ca.dst[2] = p_wo;
    ca.src[3] = ffn_w1; ca.dst[3] = p_wf1;
    ca.src[4] = ffn_w2; ca.dst[4] = p_wf2;
    ca.src[5] = pos;    ca.dst[5] = p_posr;
    cvt_multi<<<14336, 256>>>(ca);
    // 1. LN1(x2) -> fp16 tiled
    ln_kernel<<<TB, 256>>>(x2, ln1_w, ln1_b, p_ln);
    // 2. qkv = ln @ qkv_w^T -> fp32 rm
    gemm_h<0,0><<<dim3(24, 64), 512, GH_SMEM>>>(p_ln, p_wqkv, p_qkv, 3*DD, 16, nullptr, nullptr, 0);
    // 3. r_k = pos @ r_w^T -> fp16 tiled
    gemm_h<0,1><<<dim3(8, 8), 512, GH_SMEM>>>(p_posr, p_wr, p_rk, DD, 16, nullptr, nullptr, 16);
    // 4. Q/K prep + V transpose (fp16)
    qkprep_kernel<<<8192, 256>>>(p_qkv, r_w_b, r_r_b, p_qw, p_qr, p_kp);
    vtrans<<<dim3(16, 128), 256>>>(p_qkv, p_vt);
    // 5. BD_pre -> fp16 rm
    bd_h<<<dim3(8, 8, BH), 512, BD_SMEM>>>(p_qr, p_rk, p_bd);
    // 6. fused attention -> attn fp16 tiled
    flash_attn<<<dim3(8, BH), 256, FLASH_SMEM>>>(p_qw, p_kp, p_vt, p_bd, p_attn);
    // 7. y1 = attn @ o_w^T + x1 -> fp32
    gemm_h<3,0><<<dim3(8, 64), 512, GH_SMEM>>>(p_attn, p_wo, y1, DD, 16, nullptr, x1, 0);
    // 8. LN2(y1) -> fp16 tiled
    ln_kernel<<<TB, 256>>>(y1, ln2_w, ln2_b, p_ln);
    // 9. h1 = relu(ln @ ffn_w1^T + b1) -> fp16 tiled
    gemm_h<1,1><<<dim3(32, 64), 512, GH_SMEM>>>(p_ln, p_wf1, p_h1, FFD, 16, ffn_b1, nullptr, 64);
    // 10. y2 = h1 @ ffn_w2^T + b2 + x2 -> fp32
    gemm_h<2,0><<<dim3(8, 64), 512, GH_SMEM>>>(p_h1, p_wf2, y2, DD, 64, ffn_b2, x2, 0);
}